// round 9
// baseline (speedup 1.0000x reference)
#include <cuda_runtime.h>
#include <math.h>
#include <stdint.h>

#define BB 4
#define SS 2048
#define DD 1024
#define HH 16
#define DH 64
#define KDIM 1024

typedef unsigned long long ull;

// ---------------- packed f32x2 helpers (sm_100+ base PTX, no 'a' gate) ----
__device__ __forceinline__ ull bcast2(float v) {
    ull r; asm("mov.b64 %0, {%1,%1};" : "=l"(r) : "f"(v)); return r;
}
__device__ __forceinline__ void fma2(ull& d, ull a, ull b) {
    asm("fma.rn.f32x2 %0, %1, %2, %0;" : "+l"(d) : "l"(a), "l"(b));
}
__device__ __forceinline__ ull mul2(ull a, ull b) {
    ull r; asm("mul.rn.f32x2 %0, %1, %2;" : "=l"(r) : "l"(a), "l"(b)); return r;
}
__device__ __forceinline__ float2 up2(ull v) {
    float2 f; asm("mov.b64 {%0,%1}, %2;" : "=f"(f.x), "=f"(f.y) : "l"(v)); return f;
}

// ---------------- device scratch (allocation-free rule) ----------------
__device__ float g_q[BB * HH * SS * DH];    // [B,H,S,dh] head-major, RoPE'd
__device__ float g_k[BB * HH * SS * DH];
__device__ float g_v[BB * HH * SS * DH];
__device__ float g_ctx[BB * SS * DD];       // [B,S,D] attention context

// ---------------------------------------------------------------------------
// SGEMM: Y = A[M,K] @ W[N,K]^T  (both K-contiguous).  M=8192, N=K=1024.
// 128x128 block tile, 8x8 per-thread microtile, 256 threads.
// Inner product via packed fma.rn.f32x2: accumulator packed over M-pairs.
// epi: 0 = plain row-major store; 1 = head-major [B,H,S,dh]; 2 = +fused RoPE
// ---------------------------------------------------------------------------
__global__ void __launch_bounds__(256) gemm_kernel(
    const float* __restrict__ A, const float* __restrict__ W,
    float* __restrict__ Y, const int* __restrict__ pos, int epi)
{
    __shared__ float As[8][132];   // +4 pad: conflict-free transposed stores
    __shared__ float Bs[8][132];   // row base = kk*528 B (16B multiple: ok for ull2)

    const int tid = threadIdx.x;
    const int bm  = blockIdx.y * 128;
    const int bn  = blockIdx.x * 128;
    const int lr  = tid >> 1;            // load row within tile (0..127)
    const int lk  = (tid & 1) * 4;       // k offset 0 or 4
    const int tx  = tid & 15;
    const int ty  = tid >> 4;

    const float* Ap = A + (long)(bm + lr) * KDIM + lk;
    const float* Wp = W + (long)(bn + lr) * KDIM + lk;

    ull acc2[4][8];                      // [m-pair][n] ; pair = rows 2ii,2ii+1
#pragma unroll
    for (int ii = 0; ii < 4; ii++)
#pragma unroll
        for (int j = 0; j < 8; j++) acc2[ii][j] = 0ull;

    for (int k0 = 0; k0 < KDIM; k0 += 8) {
        float4 av = *(const float4*)(Ap + k0);
        float4 bv = *(const float4*)(Wp + k0);
        As[lk + 0][lr] = av.x; As[lk + 1][lr] = av.y;
        As[lk + 2][lr] = av.z; As[lk + 3][lr] = av.w;
        Bs[lk + 0][lr] = bv.x; Bs[lk + 1][lr] = bv.y;
        Bs[lk + 2][lr] = bv.z; Bs[lk + 3][lr] = bv.w;
        __syncthreads();
#pragma unroll
        for (int kk = 0; kk < 8; kk++) {
            // A pairs: natural adjacent pairs -> free packing via 16B loads
            ulonglong2 a0 = *(const ulonglong2*)&As[kk][ty * 8];
            ulonglong2 a1 = *(const ulonglong2*)&As[kk][ty * 8 + 4];
            ull ap[4] = {a0.x, a0.y, a1.x, a1.y};
            float4 b0 = *(const float4*)&Bs[kk][tx * 8];
            float4 b1 = *(const float4*)&Bs[kk][tx * 8 + 4];
            float bf[8] = {b0.x, b0.y, b0.z, b0.w, b1.x, b1.y, b1.z, b1.w};
#pragma unroll
            for (int j = 0; j < 8; j++) {
                ull bb = bcast2(bf[j]);
#pragma unroll
                for (int ii = 0; ii < 4; ii++)
                    fma2(acc2[ii][j], ap[ii], bb);
            }
        }
        __syncthreads();
    }

    // unpack to scalar tile
    float acc[8][8];
#pragma unroll
    for (int ii = 0; ii < 4; ii++)
#pragma unroll
        for (int j = 0; j < 8; j++) {
            float2 u = up2(acc2[ii][j]);
            acc[2 * ii][j]     = u.x;
            acc[2 * ii + 1][j] = u.y;
        }

    if (epi == 0) {
#pragma unroll
        for (int i = 0; i < 8; i++) {
            int m = bm + ty * 8 + i;
            float* yp = Y + (long)m * DD + bn + tx * 8;
            *(float4*)yp       = make_float4(acc[i][0], acc[i][1], acc[i][2], acc[i][3]);
            *(float4*)(yp + 4) = make_float4(acc[i][4], acc[i][5], acc[i][6], acc[i][7]);
        }
    } else {
#pragma unroll
        for (int i = 0; i < 8; i++) {
            int m  = bm + ty * 8 + i;
            int bq = m >> 11;          // m / 2048
            int sq = m & 2047;
            float p = 0.f;
            if (epi == 2) p = (float)pos[sq];
#pragma unroll
            for (int j = 0; j < 8; j += 2) {
                int n = bn + tx * 8 + j;   // even
                int h = n >> 6;
                int d = n & 63;            // even
                float x1 = acc[i][j], x2 = acc[i][j + 1];
                if (epi == 2) {
                    float fr  = powf(10000.f, -(float)(d >> 1) * (1.f / 32.f));
                    float ang = p * fr;
                    float c = cosf(ang), s = sinf(ang);
                    float o1 = x1 * c - x2 * s;
                    float o2 = x1 * s + x2 * c;
                    x1 = o1; x2 = o2;
                }
                long idx = ((long)(bq * HH + h) * SS + sq) * DH + d;
                Y[idx]     = x1;
                Y[idx + 1] = x2;
            }
        }
    }
}

// ---------------------------------------------------------------------------
// Causal flash attention (fp32, packed f32x2 math). One thread per query row;
// 128 rows per q-tile; each CTA handles the tile pair (i, 15-i) so causal
// work per CTA is constant (68 k-tiles) -- fixes tail-CTA imbalance.
// ---------------------------------------------------------------------------
__global__ void __launch_bounds__(128) attn_kernel(
    const float* __restrict__ Q, const float* __restrict__ Kx,
    const float* __restrict__ V, float* __restrict__ Ctx)
{
    __shared__ float sk[32 * 64];     // 8 KB
    __shared__ float sv[32 * 64];     // 8 KB
    __shared__ float ss[32 * 128];    // 16 KB scores: [j][thread]

    const int t  = threadIdx.x;
    const int bh = blockIdx.y;
    const float* kbase = Kx + (long)bh * SS * DH;
    const float* vbase = V  + (long)bh * SS * DH;
    const float scale = 0.125f;       // 1/sqrt(64)
    const int b = bh >> 4, h = bh & 15;

    for (int sel = 0; sel < 2; sel++) {
        const int qt   = sel ? (15 - (int)blockIdx.x) : (int)blockIdx.x;
        const int q0   = qt * 128;
        const int qrow = q0 + t;

        const float* qp = Q + ((long)bh * SS + qrow) * DH;
        ull q2[32];                                   // packed d-pairs
#pragma unroll
        for (int d2 = 0; d2 < 16; d2++) {
            ulonglong2 v = ((const ulonglong2*)qp)[d2];
            q2[2 * d2] = v.x; q2[2 * d2 + 1] = v.y;
        }
        ull o2[32];
#pragma unroll
        for (int d2 = 0; d2 < 32; d2++) o2[d2] = 0ull;
        float mrun = -INFINITY, lrun = 0.f;

        const int ktiles = (q0 >> 5) + 4;
        for (int kt = 0; kt < ktiles; kt++) {
            const int k0 = kt << 5;
            const float4* ksrc = (const float4*)(kbase + k0 * DH);
            const float4* vsrc = (const float4*)(vbase + k0 * DH);
#pragma unroll
            for (int r = 0; r < 4; r++) {
                ((float4*)sk)[t + r * 128] = ksrc[t + r * 128];
                ((float4*)sv)[t + r * 128] = vsrc[t + r * 128];
            }
            __syncthreads();

            if (k0 <= qrow) {
                float tmax = -INFINITY;
#pragma unroll 4
                for (int j = 0; j < 32; j++) {
                    const ulonglong2* kr = (const ulonglong2*)(sk + j * 64);
                    ull sa = 0ull, sb = 0ull;
#pragma unroll
                    for (int d2 = 0; d2 < 16; d2++) {
                        ulonglong2 kv = kr[d2];
                        fma2(sa, q2[2 * d2],     kv.x);
                        fma2(sb, q2[2 * d2 + 1], kv.y);
                    }
                    float2 ua = up2(sa), ub = up2(sb);
                    float s = (ua.x + ua.y) + (ub.x + ub.y);
                    s = (k0 + j <= qrow) ? s * scale : -INFINITY;
                    ss[j * 128 + t] = s;
                    tmax = fmaxf(tmax, s);
                }
                float mnew = fmaxf(mrun, tmax);
                float corr = __expf(mrun - mnew);     // first tile: exp(-inf)=0
                ull corr2 = bcast2(corr);
#pragma unroll
                for (int d2 = 0; d2 < 32; d2++) o2[d2] = mul2(o2[d2], corr2);
                lrun *= corr;
#pragma unroll 2
                for (int j = 0; j < 32; j++) {
                    float pj = __expf(ss[j * 128 + t] - mnew);
                    lrun += pj;
                    ull pj2 = bcast2(pj);
                    const ulonglong2* vr = (const ulonglong2*)(sv + j * 64);
#pragma unroll
                    for (int d2 = 0; d2 < 16; d2++) {
                        ulonglong2 vv = vr[d2];
                        fma2(o2[2 * d2],     pj2, vv.x);
                        fma2(o2[2 * d2 + 1], pj2, vv.y);
                    }
                }
                mrun = mnew;
            }
            __syncthreads();
        }

        ull inv2 = bcast2(1.f / lrun);
        float* op = Ctx + (((long)b * SS + qrow) * HH + h) * DH;
#pragma unroll
        for (int d2 = 0; d2 < 16; d2++) {
            ulonglong2 v;
            v.x = mul2(o2[2 * d2],     inv2);
            v.y = mul2(o2[2 * d2 + 1], inv2);
            ((ulonglong2*)op)[d2] = v;
        }
    }
}

// ---------------------------------------------------------------------------
extern "C" void kernel_launch(void* const* d_in, const int* in_sizes, int n_in,
                              void* d_out, int out_size)
{
    (void)in_sizes; (void)n_in; (void)out_size;
    const float* x   = (const float*)d_in[0];   // in_features [B,S,D]
    const int*   pos = (const int*)  d_in[1];   // token_positions [S]
    const float* wq  = (const float*)d_in[2];
    const float* wk  = (const float*)d_in[3];
    const float* wv  = (const float*)d_in[4];
    const float* wo  = (const float*)d_in[5];
    float* out = (float*)d_out;

    float *qb, *kb, *vb, *cb;
    cudaGetSymbolAddress((void**)&qb, g_q);
    cudaGetSymbolAddress((void**)&kb, g_k);
    cudaGetSymbolAddress((void**)&vb, g_v);
    cudaGetSymbolAddress((void**)&cb, g_ctx);

    dim3 gg(DD / 128, (BB * SS) / 128);   // 8 x 64
    gemm_kernel<<<gg, 256>>>(x, wq, qb, pos, 2);   // Q + RoPE, head-major
    gemm_kernel<<<gg, 256>>>(x, wk, kb, pos, 2);   // K + RoPE, head-major
    gemm_kernel<<<gg, 256>>>(x, wv, vb, pos, 1);   // V, head-major

    dim3 ga(8, BB * HH);                  // paired causal tiles (i, 15-i)
    attn_kernel<<<ga, 128>>>(qb, kb, vb, cb);

    gemm_kernel<<<gg, 256>>>(cb, wo, out, pos, 0); // output projection
}

// round 10
// speedup vs baseline: 2.3547x; 2.3547x over previous
#include <cuda_runtime.h>
#include <cuda_bf16.h>
#include <math.h>
#include <stdint.h>

#define BB 4
#define SS 2048
#define DD 1024
#define HH 16
#define DH 64
#define KDIM 1024

// ---------------- device scratch (allocation-free rule) ----------------
__device__ float g_q[BB * HH * SS * DH];          // [B,H,S,dh] RoPE'd
__device__ float g_k[BB * HH * SS * DH];
__device__ float g_v[BB * HH * SS * DH];
__device__ float g_ctx[BB * SS * DD];             // attention context [B,S,D]
__device__ __nv_bfloat16 g_xh[BB * SS * DD];      // input hi/lo bf16 split
__device__ __nv_bfloat16 g_xl[BB * SS * DD];
__device__ __nv_bfloat16 g_ch[BB * SS * DD];      // ctx hi/lo split
__device__ __nv_bfloat16 g_cl[BB * SS * DD];
__device__ __nv_bfloat16 g_wh[4][DD * DD];        // wq,wk,wv,wo hi
__device__ __nv_bfloat16 g_wl[4][DD * DD];        // lo

// ---------------------------------------------------------------------------
// fp32 -> (hi, lo) bf16 split, vectorized by 4
// ---------------------------------------------------------------------------
__global__ void split_kernel(const float* __restrict__ s,
                             __nv_bfloat16* __restrict__ hi,
                             __nv_bfloat16* __restrict__ lo, int n4) {
    int i = blockIdx.x * blockDim.x + threadIdx.x;
    if (i >= n4) return;
    float4 v = ((const float4*)s)[i];
    __nv_bfloat16 h0 = __float2bfloat16(v.x);
    __nv_bfloat16 h1 = __float2bfloat16(v.y);
    __nv_bfloat16 h2 = __float2bfloat16(v.z);
    __nv_bfloat16 h3 = __float2bfloat16(v.w);
    __nv_bfloat16 l0 = __float2bfloat16(v.x - __bfloat162float(h0));
    __nv_bfloat16 l1 = __float2bfloat16(v.y - __bfloat162float(h1));
    __nv_bfloat16 l2 = __float2bfloat16(v.z - __bfloat162float(h2));
    __nv_bfloat16 l3 = __float2bfloat16(v.w - __bfloat162float(h3));
    ((__nv_bfloat162*)hi)[2 * i]     = __halves2bfloat162(h0, h1);
    ((__nv_bfloat162*)hi)[2 * i + 1] = __halves2bfloat162(h2, h3);
    ((__nv_bfloat162*)lo)[2 * i]     = __halves2bfloat162(l0, l1);
    ((__nv_bfloat162*)lo)[2 * i + 1] = __halves2bfloat162(l2, l3);
}

// ---------------------------------------------------------------------------
// mma.sync bf16x3 GEMM: Y[M,N] = A[M,K] @ W[N,K]^T,  fp32 accum.
// CTA tile 128x128, 8 warps (2m x 4n), warp tile 64x32 = 4x4 m16n8 frags.
// D += Ah*Wh + Ah*Wl + Al*Wh   (bf16x3 split; residual ~1e-5 rel)
// epi: 0 = row-major store, 1 = head-major [B,H,S,dh], 2 = +fused RoPE
// SMEM rows padded to 40 bf16 (80 B) -> conflict-free b32 fragment loads.
// ---------------------------------------------------------------------------
#define SROW 80                      // bytes per smem row (32 bf16 + 8 pad)
#define STILE (128 * SROW)           // 10240 B per tile
#define GSMEM (4 * STILE)            // 40960 B total (< 48KB default)

__device__ __forceinline__ void mma16816(float* c, const uint32_t* a,
                                         const uint32_t* b) {
    asm volatile(
        "mma.sync.aligned.m16n8k16.row.col.f32.bf16.bf16.f32 "
        "{%0,%1,%2,%3}, {%4,%5,%6,%7}, {%8,%9}, {%0,%1,%2,%3};"
        : "+f"(c[0]), "+f"(c[1]), "+f"(c[2]), "+f"(c[3])
        : "r"(a[0]), "r"(a[1]), "r"(a[2]), "r"(a[3]), "r"(b[0]), "r"(b[1]));
}

__global__ void __launch_bounds__(256) gemm_mma(
    const __nv_bfloat16* __restrict__ ah, const __nv_bfloat16* __restrict__ al,
    const __nv_bfloat16* __restrict__ wh, const __nv_bfloat16* __restrict__ wl,
    float* __restrict__ Y, const int* __restrict__ pos, int epi)
{
    extern __shared__ char smc[];
    char* pAh = smc;
    char* pAl = smc + STILE;
    char* pWh = smc + 2 * STILE;
    char* pWl = smc + 3 * STILE;

    const int tid = threadIdx.x;
    const int w = tid >> 5, l = tid & 31;
    const int g = l >> 2, t = l & 3;
    const int wm = (w & 1) * 64, wn = (w >> 1) * 32;
    const int bm = blockIdx.y * 128, bn = blockIdx.x * 128;

    // loader: 2 threads per row, each covers 16 bf16 (32 B)
    const int lr = tid >> 1, chf = tid & 1;
    const long arow = (long)(bm + lr) * KDIM + chf * 16;
    const long wrow = (long)(bn + lr) * KDIM + chf * 16;
    const int soff = lr * SROW + chf * 32;

    float acc[4][4][4];
#pragma unroll
    for (int mt = 0; mt < 4; mt++)
#pragma unroll
        for (int nt = 0; nt < 4; nt++)
#pragma unroll
            for (int e = 0; e < 4; e++) acc[mt][nt][e] = 0.f;

    for (int k0 = 0; k0 < KDIM; k0 += 32) {
        // global -> smem (16 bf16 = 2 x float4 per array per thread)
        {
            const float4* s0 = (const float4*)(ah + arow + k0);
            const float4* s1 = (const float4*)(al + arow + k0);
            const float4* s2 = (const float4*)(wh + wrow + k0);
            const float4* s3 = (const float4*)(wl + wrow + k0);
            *(float4*)(pAh + soff)      = s0[0];
            *(float4*)(pAh + soff + 16) = s0[1];
            *(float4*)(pAl + soff)      = s1[0];
            *(float4*)(pAl + soff + 16) = s1[1];
            *(float4*)(pWh + soff)      = s2[0];
            *(float4*)(pWh + soff + 16) = s2[1];
            *(float4*)(pWl + soff)      = s3[0];
            *(float4*)(pWl + soff + 16) = s3[1];
        }
        __syncthreads();

#pragma unroll
        for (int ks = 0; ks < 2; ks++) {
            const int kb = (ks * 16 + t * 2) * 2;   // byte col of this lane
            // W fragments (b0: k 0-7, b1: k 8-15 => +16 B)
            uint32_t Bh[4][2], Bl[4][2];
#pragma unroll
            for (int nt = 0; nt < 4; nt++) {
                int off = (wn + nt * 8 + g) * SROW + kb;
                Bh[nt][0] = *(const uint32_t*)(pWh + off);
                Bh[nt][1] = *(const uint32_t*)(pWh + off + 16);
                Bl[nt][0] = *(const uint32_t*)(pWl + off);
                Bl[nt][1] = *(const uint32_t*)(pWl + off + 16);
            }
#pragma unroll
            for (int mt = 0; mt < 4; mt++) {
                int off0 = (wm + mt * 16 + g) * SROW + kb;
                int off1 = off0 + 8 * SROW;
                uint32_t Ah4[4] = { *(const uint32_t*)(pAh + off0),
                                    *(const uint32_t*)(pAh + off1),
                                    *(const uint32_t*)(pAh + off0 + 16),
                                    *(const uint32_t*)(pAh + off1 + 16) };
                uint32_t Al4[4] = { *(const uint32_t*)(pAl + off0),
                                    *(const uint32_t*)(pAl + off1),
                                    *(const uint32_t*)(pAl + off0 + 16),
                                    *(const uint32_t*)(pAl + off1 + 16) };
#pragma unroll
                for (int nt = 0; nt < 4; nt++) {
                    mma16816(acc[mt][nt], Ah4, Bh[nt]);
                    mma16816(acc[mt][nt], Ah4, Bl[nt]);
                    mma16816(acc[mt][nt], Al4, Bh[nt]);
                }
            }
        }
        __syncthreads();
    }

    // epilogue: lane holds rows {m0, m0+8}, cols {n, n+1} per fragment
#pragma unroll
    for (int mt = 0; mt < 4; mt++) {
        const int m0 = bm + wm + mt * 16 + g;
#pragma unroll
        for (int nt = 0; nt < 4; nt++) {
            const int n = bn + wn + nt * 8 + t * 2;   // even
            float c0 = acc[mt][nt][0], c1 = acc[mt][nt][1];
            float c2 = acc[mt][nt][2], c3 = acc[mt][nt][3];
            if (epi == 0) {
                *(float2*)(Y + (long)m0 * DD + n)       = make_float2(c0, c1);
                *(float2*)(Y + (long)(m0 + 8) * DD + n) = make_float2(c2, c3);
            } else {
                const int h = n >> 6, d = n & 63;      // d even
#pragma unroll
                for (int half = 0; half < 2; half++) {
                    int m  = m0 + half * 8;
                    int bq = m >> 11, sq = m & 2047;
                    float x1 = half ? c2 : c0;
                    float x2 = half ? c3 : c1;
                    if (epi == 2) {
                        float fr  = powf(10000.f, -(float)(d >> 1) * (1.f / 32.f));
                        float ang = (float)pos[sq] * fr;
                        float cc = cosf(ang), sn = sinf(ang);
                        float o1 = x1 * cc - x2 * sn;
                        float o2 = x1 * sn + x2 * cc;
                        x1 = o1; x2 = o2;
                    }
                    long idx = ((long)(bq * HH + h) * SS + sq) * DH + d;
                    *(float2*)(Y + idx) = make_float2(x1, x2);
                }
            }
        }
    }
}

// ---------------------------------------------------------------------------
// Causal flash attention (scalar fp32 -- proven round-2 numerics).
// One thread per query row; 128 rows/tile; each CTA handles the paired
// q-tiles (i, 15-i) so causal work per CTA is constant (68 k-tiles).
// ---------------------------------------------------------------------------
__global__ void __launch_bounds__(128) attn_kernel(
    const float* __restrict__ Q, const float* __restrict__ Kx,
    const float* __restrict__ V, float* __restrict__ Ctx)
{
    __shared__ float sk[32 * 64];     // 8 KB
    __shared__ float sv[32 * 64];     // 8 KB
    __shared__ float ss[32 * 128];    // 16 KB scores: [j][thread]

    const int t  = threadIdx.x;
    const int bh = blockIdx.y;
    const float* kbase = Kx + (long)bh * SS * DH;
    const float* vbase = V  + (long)bh * SS * DH;
    const float scale = 0.125f;       // 1/sqrt(64)
    const int b = bh >> 4, h = bh & 15;

    for (int sel = 0; sel < 2; sel++) {
        const int qt   = sel ? (15 - (int)blockIdx.x) : (int)blockIdx.x;
        const int q0   = qt * 128;
        const int qrow = q0 + t;

        const float* qp = Q + ((long)bh * SS + qrow) * DH;
        float q[64];
#pragma unroll
        for (int d4 = 0; d4 < 16; d4++) {
            float4 v = *(const float4*)(qp + d4 * 4);
            q[d4 * 4 + 0] = v.x; q[d4 * 4 + 1] = v.y;
            q[d4 * 4 + 2] = v.z; q[d4 * 4 + 3] = v.w;
        }
        float o[64];
#pragma unroll
        for (int d = 0; d < 64; d++) o[d] = 0.f;
        float mrun = -INFINITY, lrun = 0.f;

        const int ktiles = (q0 >> 5) + 4;
        for (int kt = 0; kt < ktiles; kt++) {
            const int k0 = kt << 5;
            const float4* ksrc = (const float4*)(kbase + k0 * DH);
            const float4* vsrc = (const float4*)(vbase + k0 * DH);
#pragma unroll
            for (int r = 0; r < 4; r++) {
                ((float4*)sk)[t + r * 128] = ksrc[t + r * 128];
                ((float4*)sv)[t + r * 128] = vsrc[t + r * 128];
            }
            __syncthreads();

            if (k0 <= qrow) {
                float tmax = -INFINITY;
#pragma unroll 4
                for (int j = 0; j < 32; j++) {
                    const float4* kr = (const float4*)(sk + j * 64);
                    float s0 = 0.f, s1 = 0.f, s2 = 0.f, s3 = 0.f;
#pragma unroll
                    for (int d4 = 0; d4 < 16; d4++) {
                        float4 kv = kr[d4];
                        s0 = fmaf(q[d4 * 4 + 0], kv.x, s0);
                        s1 = fmaf(q[d4 * 4 + 1], kv.y, s1);
                        s2 = fmaf(q[d4 * 4 + 2], kv.z, s2);
                        s3 = fmaf(q[d4 * 4 + 3], kv.w, s3);
                    }
                    float s = (s0 + s1) + (s2 + s3);
                    s = (k0 + j <= qrow) ? s * scale : -INFINITY;
                    ss[j * 128 + t] = s;
                    tmax = fmaxf(tmax, s);
                }
                float mnew = fmaxf(mrun, tmax);
                float corr = __expf(mrun - mnew);   // first tile: exp(-inf)=0
#pragma unroll
                for (int d = 0; d < 64; d++) o[d] *= corr;
                lrun *= corr;
#pragma unroll 2
                for (int j = 0; j < 32; j++) {
                    float pj = __expf(ss[j * 128 + t] - mnew);
                    lrun += pj;
                    const float4* vr = (const float4*)(sv + j * 64);
#pragma unroll
                    for (int d4 = 0; d4 < 16; d4++) {
                        float4 vv = vr[d4];
                        o[d4 * 4 + 0] = fmaf(pj, vv.x, o[d4 * 4 + 0]);
                        o[d4 * 4 + 1] = fmaf(pj, vv.y, o[d4 * 4 + 1]);
                        o[d4 * 4 + 2] = fmaf(pj, vv.z, o[d4 * 4 + 2]);
                        o[d4 * 4 + 3] = fmaf(pj, vv.w, o[d4 * 4 + 3]);
                    }
                }
                mrun = mnew;
            }
            __syncthreads();
        }

        float inv = 1.f / lrun;
        float* op = Ctx + (((long)b * SS + qrow) * HH + h) * DH;
#pragma unroll
        for (int d4 = 0; d4 < 16; d4++) {
            float4 v;
            v.x = o[d4 * 4 + 0] * inv; v.y = o[d4 * 4 + 1] * inv;
            v.z = o[d4 * 4 + 2] * inv; v.w = o[d4 * 4 + 3] * inv;
            *(float4*)(op + d4 * 4) = v;
        }
    }
}

// ---------------------------------------------------------------------------
extern "C" void kernel_launch(void* const* d_in, const int* in_sizes, int n_in,
                              void* d_out, int out_size)
{
    (void)in_sizes; (void)n_in; (void)out_size;
    const float* x   = (const float*)d_in[0];   // in_features [B,S,D]
    const int*   pos = (const int*)  d_in[1];   // token_positions [S]
    const float* w[4] = { (const float*)d_in[2], (const float*)d_in[3],
                          (const float*)d_in[4], (const float*)d_in[5] };
    float* out = (float*)d_out;

    float *qb, *kb, *vb, *cb;
    __nv_bfloat16 *xh, *xl, *ch, *cl, *wh, *wl;
    cudaGetSymbolAddress((void**)&qb, g_q);
    cudaGetSymbolAddress((void**)&kb, g_k);
    cudaGetSymbolAddress((void**)&vb, g_v);
    cudaGetSymbolAddress((void**)&cb, g_ctx);
    cudaGetSymbolAddress((void**)&xh, g_xh);
    cudaGetSymbolAddress((void**)&xl, g_xl);
    cudaGetSymbolAddress((void**)&ch, g_ch);
    cudaGetSymbolAddress((void**)&cl, g_cl);
    cudaGetSymbolAddress((void**)&wh, g_wh);
    cudaGetSymbolAddress((void**)&wl, g_wl);

    // fp32 -> bf16 hi/lo splits
    const int nX4 = BB * SS * DD / 4;
    split_kernel<<<(nX4 + 255) / 256, 256>>>(x, xh, xl, nX4);
    const int nW4 = DD * DD / 4;
    for (int i = 0; i < 4; i++)
        split_kernel<<<(nW4 + 255) / 256, 256>>>(w[i], wh + (size_t)i * DD * DD,
                                                 wl + (size_t)i * DD * DD, nW4);

    dim3 gg(DD / 128, (BB * SS) / 128);   // 8 x 64
    gemm_mma<<<gg, 256, GSMEM>>>(xh, xl, wh + 0 * (size_t)DD * DD,
                                 wl + 0 * (size_t)DD * DD, qb, pos, 2); // Q+RoPE
    gemm_mma<<<gg, 256, GSMEM>>>(xh, xl, wh + 1 * (size_t)DD * DD,
                                 wl + 1 * (size_t)DD * DD, kb, pos, 2); // K+RoPE
    gemm_mma<<<gg, 256, GSMEM>>>(xh, xl, wh + 2 * (size_t)DD * DD,
                                 wl + 2 * (size_t)DD * DD, vb, pos, 1); // V

    dim3 ga(8, BB * HH);                  // paired causal tiles (i, 15-i)
    attn_kernel<<<ga, 128>>>(qb, kb, vb, cb);

    split_kernel<<<(nX4 + 255) / 256, 256>>>(cb, ch, cl, nX4);
    gemm_mma<<<gg, 256, GSMEM>>>(ch, cl, wh + 3 * (size_t)DD * DD,
                                 wl + 3 * (size_t)DD * DD, out, pos, 0); // Wo
}

// round 11
// speedup vs baseline: 3.5646x; 1.5138x over previous
#include <cuda_runtime.h>
#include <cuda_bf16.h>
#include <math.h>
#include <stdint.h>

#define BB 4
#define SS 2048
#define DD 1024
#define HH 16
#define DH 64
#define KDIM 1024

typedef __nv_bfloat16 bf16;

// ---------------- device scratch (allocation-free rule) ----------------
__device__ bf16 g_qh[BB * HH * SS * DH];   // Q RoPE'd, head-major, hi/lo
__device__ bf16 g_ql[BB * HH * SS * DH];
__device__ bf16 g_kh[BB * HH * SS * DH];
__device__ bf16 g_kl[BB * HH * SS * DH];
__device__ bf16 g_vh[BB * HH * SS * DH];
__device__ bf16 g_vl[BB * HH * SS * DH];
__device__ bf16 g_xh[BB * SS * DD];        // input hi/lo split
__device__ bf16 g_xl[BB * SS * DD];
__device__ bf16 g_ch[BB * SS * DD];        // attention ctx hi/lo (written by attn)
__device__ bf16 g_cl[BB * SS * DD];
__device__ bf16 g_wh[4][DD * DD];          // wq,wk,wv,wo hi
__device__ bf16 g_wl[4][DD * DD];          // lo

// ---------------------------------------------------------------------------
__device__ __forceinline__ void mma16816(float* c, const uint32_t* a,
                                         const uint32_t* b) {
    asm volatile(
        "mma.sync.aligned.m16n8k16.row.col.f32.bf16.bf16.f32 "
        "{%0,%1,%2,%3}, {%4,%5,%6,%7}, {%8,%9}, {%0,%1,%2,%3};"
        : "+f"(c[0]), "+f"(c[1]), "+f"(c[2]), "+f"(c[3])
        : "r"(a[0]), "r"(a[1]), "r"(a[2]), "r"(a[3]), "r"(b[0]), "r"(b[1]));
}
__device__ __forceinline__ uint32_t pack_bf2(float lo, float hi) {
    __nv_bfloat162 t = __floats2bfloat162_rn(lo, hi);   // .x = lo element
    return *(uint32_t*)&t;
}

// ---------------------------------------------------------------------------
// fp32 -> (hi, lo) bf16 split, vectorized by 4
// ---------------------------------------------------------------------------
__global__ void split_kernel(const float* __restrict__ s,
                             bf16* __restrict__ hi, bf16* __restrict__ lo,
                             int n4) {
    int i = blockIdx.x * blockDim.x + threadIdx.x;
    if (i >= n4) return;
    float4 v = ((const float4*)s)[i];
    bf16 h0 = __float2bfloat16(v.x), h1 = __float2bfloat16(v.y);
    bf16 h2 = __float2bfloat16(v.z), h3 = __float2bfloat16(v.w);
    bf16 l0 = __float2bfloat16(v.x - __bfloat162float(h0));
    bf16 l1 = __float2bfloat16(v.y - __bfloat162float(h1));
    bf16 l2 = __float2bfloat16(v.z - __bfloat162float(h2));
    bf16 l3 = __float2bfloat16(v.w - __bfloat162float(h3));
    ((__nv_bfloat162*)hi)[2 * i]     = __halves2bfloat162(h0, h1);
    ((__nv_bfloat162*)hi)[2 * i + 1] = __halves2bfloat162(h2, h3);
    ((__nv_bfloat162*)lo)[2 * i]     = __halves2bfloat162(l0, l1);
    ((__nv_bfloat162*)lo)[2 * i + 1] = __halves2bfloat162(l2, l3);
}

// ---------------------------------------------------------------------------
// mma.sync bf16x3 GEMM (proven round-9 core): Y = A[M,K] @ W[N,K]^T.
// epi: 0 = fp32 row-major store to Y
//      1 = bf16 hi/lo head-major store to (Yh,Yl)
//      2 = same + fused RoPE
// ---------------------------------------------------------------------------
#define SROW 80
#define STILE (128 * SROW)
#define GSMEM (4 * STILE)

__global__ void __launch_bounds__(256) gemm_mma(
    const bf16* __restrict__ ah, const bf16* __restrict__ al,
    const bf16* __restrict__ wh, const bf16* __restrict__ wl,
    float* __restrict__ Y, bf16* __restrict__ Yh, bf16* __restrict__ Yl,
    const int* __restrict__ pos, int epi)
{
    extern __shared__ char smc[];
    char* pAh = smc;
    char* pAl = smc + STILE;
    char* pWh = smc + 2 * STILE;
    char* pWl = smc + 3 * STILE;

    const int tid = threadIdx.x;
    const int w = tid >> 5, l = tid & 31;
    const int g = l >> 2, t = l & 3;
    const int wm = (w & 1) * 64, wn = (w >> 1) * 32;
    const int bm = blockIdx.y * 128, bn = blockIdx.x * 128;

    const int lr = tid >> 1, chf = tid & 1;
    const long arow = (long)(bm + lr) * KDIM + chf * 16;
    const long wrow = (long)(bn + lr) * KDIM + chf * 16;
    const int soff = lr * SROW + chf * 32;

    float acc[4][4][4];
#pragma unroll
    for (int mt = 0; mt < 4; mt++)
#pragma unroll
        for (int nt = 0; nt < 4; nt++)
#pragma unroll
            for (int e = 0; e < 4; e++) acc[mt][nt][e] = 0.f;

    for (int k0 = 0; k0 < KDIM; k0 += 32) {
        {
            const float4* s0 = (const float4*)(ah + arow + k0);
            const float4* s1 = (const float4*)(al + arow + k0);
            const float4* s2 = (const float4*)(wh + wrow + k0);
            const float4* s3 = (const float4*)(wl + wrow + k0);
            *(float4*)(pAh + soff)      = s0[0];
            *(float4*)(pAh + soff + 16) = s0[1];
            *(float4*)(pAl + soff)      = s1[0];
            *(float4*)(pAl + soff + 16) = s1[1];
            *(float4*)(pWh + soff)      = s2[0];
            *(float4*)(pWh + soff + 16) = s2[1];
            *(float4*)(pWl + soff)      = s3[0];
            *(float4*)(pWl + soff + 16) = s3[1];
        }
        __syncthreads();

#pragma unroll
        for (int ks = 0; ks < 2; ks++) {
            const int kb = (ks * 16 + t * 2) * 2;
            uint32_t Bh[4][2], Bl[4][2];
#pragma unroll
            for (int nt = 0; nt < 4; nt++) {
                int off = (wn + nt * 8 + g) * SROW + kb;
                Bh[nt][0] = *(const uint32_t*)(pWh + off);
                Bh[nt][1] = *(const uint32_t*)(pWh + off + 16);
                Bl[nt][0] = *(const uint32_t*)(pWl + off);
                Bl[nt][1] = *(const uint32_t*)(pWl + off + 16);
            }
#pragma unroll
            for (int mt = 0; mt < 4; mt++) {
                int off0 = (wm + mt * 16 + g) * SROW + kb;
                int off1 = off0 + 8 * SROW;
                uint32_t Ah4[4] = { *(const uint32_t*)(pAh + off0),
                                    *(const uint32_t*)(pAh + off1),
                                    *(const uint32_t*)(pAh + off0 + 16),
                                    *(const uint32_t*)(pAh + off1 + 16) };
                uint32_t Al4[4] = { *(const uint32_t*)(pAl + off0),
                                    *(const uint32_t*)(pAl + off1),
                                    *(const uint32_t*)(pAl + off0 + 16),
                                    *(const uint32_t*)(pAl + off1 + 16) };
#pragma unroll
                for (int nt = 0; nt < 4; nt++) {
                    mma16816(acc[mt][nt], Ah4, Bh[nt]);
                    mma16816(acc[mt][nt], Ah4, Bl[nt]);
                    mma16816(acc[mt][nt], Al4, Bh[nt]);
                }
            }
        }
        __syncthreads();
    }

#pragma unroll
    for (int mt = 0; mt < 4; mt++) {
        const int m0 = bm + wm + mt * 16 + g;
#pragma unroll
        for (int nt = 0; nt < 4; nt++) {
            const int n = bn + wn + nt * 8 + t * 2;   // even
            float c0 = acc[mt][nt][0], c1 = acc[mt][nt][1];
            float c2 = acc[mt][nt][2], c3 = acc[mt][nt][3];
            if (epi == 0) {
                *(float2*)(Y + (long)m0 * DD + n)       = make_float2(c0, c1);
                *(float2*)(Y + (long)(m0 + 8) * DD + n) = make_float2(c2, c3);
            } else {
                const int h = n >> 6, d = n & 63;      // d even
#pragma unroll
                for (int half = 0; half < 2; half++) {
                    int m  = m0 + half * 8;
                    int bq = m >> 11, sq = m & 2047;
                    float x1 = half ? c2 : c0;
                    float x2 = half ? c3 : c1;
                    if (epi == 2) {
                        float fr  = powf(10000.f, -(float)(d >> 1) * (1.f / 32.f));
                        float ang = (float)pos[sq] * fr;
                        float cc = cosf(ang), sn = sinf(ang);
                        float o1 = x1 * cc - x2 * sn;
                        float o2 = x1 * sn + x2 * cc;
                        x1 = o1; x2 = o2;
                    }
                    long idx = ((long)(bq * HH + h) * SS + sq) * DH + d;
                    bf16 h1 = __float2bfloat16(x1);
                    bf16 h2 = __float2bfloat16(x2);
                    *(uint32_t*)(Yh + idx) =
                        pack_bf2(x1, x2) * 0 + // (avoid double rounding path below)
                        (*(uint32_t*)&(__nv_bfloat162&)*(
                            &(const __nv_bfloat162&)__halves2bfloat162(h1, h2)));
                    bf16 l1 = __float2bfloat16(x1 - __bfloat162float(h1));
                    bf16 l2 = __float2bfloat16(x2 - __bfloat162float(h2));
                    __nv_bfloat162 lp = __halves2bfloat162(l1, l2);
                    *(uint32_t*)(Yl + idx) = *(uint32_t*)&lp;
                }
            }
        }
    }
}

// ---------------------------------------------------------------------------
// MMA flash attention: CTA = 64 q rows (4 warps x 16), k-tile = 32 keys.
// bf16x3 for both QK^T and PV; fp32 softmax; P stays in registers.
// K staged K-major (stride 72), V staged transposed [d][key] (stride 40),
// double-buffered, one __syncthreads per tile.
// CTA pairs causal q-tiles (qi, 31-qi) -> constant 68 k-tiles per CTA.
// Writes ctx directly as bf16 hi/lo in [B,S,H*dh].
// ---------------------------------------------------------------------------
__global__ void __launch_bounds__(128) attn_mma(
    const bf16* __restrict__ Qh, const bf16* __restrict__ Ql,
    const bf16* __restrict__ Kh, const bf16* __restrict__ Kl,
    const bf16* __restrict__ Vh, const bf16* __restrict__ Vl,
    bf16* __restrict__ Ch, bf16* __restrict__ Cl)
{
    __shared__ __align__(16) bf16 sKh[2][32][72];
    __shared__ __align__(16) bf16 sKl[2][32][72];
    __shared__ __align__(16) bf16 sVh[2][64][40];   // transposed [d][key]
    __shared__ __align__(16) bf16 sVl[2][64][40];

    const int tid = threadIdx.x;
    const int w = tid >> 5, l = tid & 31;
    const int g = l >> 2, t = l & 3;
    const int bh = blockIdx.y, b = bh >> 4, h = bh & 15;
    const long hoff = (long)bh * SS * DH;

    const int krow = tid >> 2, kseg = tid & 3;      // K staging: row, 16-elem seg
    const int vkp = tid & 15, vdc = tid >> 4;       // V staging: key-pair, d-chunk(8)
    const float scale = 0.125f;

    for (int sel = 0; sel < 2; sel++) {
        const int qi = sel ? 31 - (int)blockIdx.x : (int)blockIdx.x;
        const int q0 = qi * 64;
        const int r0 = q0 + w * 16 + g;
        const int r1 = r0 + 8;

        // Q fragments from global (bf16 hi/lo)
        uint32_t qfh[4][4], qfl[4][4];
        {
            const bf16* p0h = Qh + hoff + (long)r0 * DH;
            const bf16* p1h = Qh + hoff + (long)r1 * DH;
            const bf16* p0l = Ql + hoff + (long)r0 * DH;
            const bf16* p1l = Ql + hoff + (long)r1 * DH;
#pragma unroll
            for (int kc = 0; kc < 4; kc++) {
                int o0 = kc * 16 + 2 * t;
                qfh[kc][0] = *(const uint32_t*)(p0h + o0);
                qfh[kc][1] = *(const uint32_t*)(p1h + o0);
                qfh[kc][2] = *(const uint32_t*)(p0h + o0 + 8);
                qfh[kc][3] = *(const uint32_t*)(p1h + o0 + 8);
                qfl[kc][0] = *(const uint32_t*)(p0l + o0);
                qfl[kc][1] = *(const uint32_t*)(p1l + o0);
                qfl[kc][2] = *(const uint32_t*)(p0l + o0 + 8);
                qfl[kc][3] = *(const uint32_t*)(p1l + o0 + 8);
            }
        }

        float o[8][4];
#pragma unroll
        for (int nf = 0; nf < 8; nf++)
#pragma unroll
            for (int e = 0; e < 4; e++) o[nf][e] = 0.f;
        float mrun0 = -INFINITY, mrun1 = -INFINITY;
        float lrun0 = 0.f, lrun1 = 0.f;

        const int ktiles = 2 * qi + 2;
        for (int kt = 0; kt < ktiles; kt++) {
            const int k0 = kt * 32;
            const int buf = kt & 1;

            // --- stage K (K-major) ---
            {
                const float4* sh = (const float4*)(Kh + hoff +
                                   (long)(k0 + krow) * DH + kseg * 16);
                const float4* sl = (const float4*)(Kl + hoff +
                                   (long)(k0 + krow) * DH + kseg * 16);
                *(float4*)&sKh[buf][krow][kseg * 16]     = sh[0];
                *(float4*)&sKh[buf][krow][kseg * 16 + 8] = sh[1];
                *(float4*)&sKl[buf][krow][kseg * 16]     = sl[0];
                *(float4*)&sKl[buf][krow][kseg * 16 + 8] = sl[1];
            }
            // --- stage V transposed [d][key] ---
            {
                const uint32_t* r0h = (const uint32_t*)(Vh + hoff +
                                      (long)(k0 + 2 * vkp) * DH + vdc * 8);
                const uint32_t* r1h = (const uint32_t*)(Vh + hoff +
                                      (long)(k0 + 2 * vkp + 1) * DH + vdc * 8);
                const uint32_t* r0l = (const uint32_t*)(Vl + hoff +
                                      (long)(k0 + 2 * vkp) * DH + vdc * 8);
                const uint32_t* r1l = (const uint32_t*)(Vl + hoff +
                                      (long)(k0 + 2 * vkp + 1) * DH + vdc * 8);
#pragma unroll
                for (int m = 0; m < 4; m++) {     // 4 u32 = 8 bf16 along d
                    uint32_t ah_ = r0h[m], bh_ = r1h[m];
                    uint32_t al_ = r0l[m], bl_ = r1l[m];
                    int d0 = vdc * 8 + 2 * m;
                    *(uint32_t*)&sVh[buf][d0][2 * vkp]     = __byte_perm(ah_, bh_, 0x5410);
                    *(uint32_t*)&sVh[buf][d0 + 1][2 * vkp] = __byte_perm(ah_, bh_, 0x7632);
                    *(uint32_t*)&sVl[buf][d0][2 * vkp]     = __byte_perm(al_, bl_, 0x5410);
                    *(uint32_t*)&sVl[buf][d0 + 1][2 * vkp] = __byte_perm(al_, bl_, 0x7632);
                }
            }
            __syncthreads();

            // --- scores: S[16x32] = Q @ K^T (bf16x3) ---
            float sc[4][4];
#pragma unroll
            for (int nf = 0; nf < 4; nf++) {
#pragma unroll
                for (int e = 0; e < 4; e++) sc[nf][e] = 0.f;
#pragma unroll
                for (int kc = 0; kc < 4; kc++) {
                    const bf16* kh_ = &sKh[buf][nf * 8 + g][kc * 16 + 2 * t];
                    const bf16* kl_ = &sKl[buf][nf * 8 + g][kc * 16 + 2 * t];
                    uint32_t Bh2[2] = { *(const uint32_t*)kh_,
                                        *(const uint32_t*)(kh_ + 8) };
                    uint32_t Bl2[2] = { *(const uint32_t*)kl_,
                                        *(const uint32_t*)(kl_ + 8) };
                    mma16816(sc[nf], qfh[kc], Bh2);
                    mma16816(sc[nf], qfh[kc], Bl2);
                    mma16816(sc[nf], qfl[kc], Bh2);
                }
            }
            // --- scale + causal mask ---
            float rmax0 = -INFINITY, rmax1 = -INFINITY;
#pragma unroll
            for (int nf = 0; nf < 4; nf++) {
                int cb = k0 + nf * 8 + 2 * t;
                sc[nf][0] = (cb     <= r0) ? sc[nf][0] * scale : -INFINITY;
                sc[nf][1] = (cb + 1 <= r0) ? sc[nf][1] * scale : -INFINITY;
                sc[nf][2] = (cb     <= r1) ? sc[nf][2] * scale : -INFINITY;
                sc[nf][3] = (cb + 1 <= r1) ? sc[nf][3] * scale : -INFINITY;
                rmax0 = fmaxf(rmax0, fmaxf(sc[nf][0], sc[nf][1]));
                rmax1 = fmaxf(rmax1, fmaxf(sc[nf][2], sc[nf][3]));
            }
            rmax0 = fmaxf(rmax0, __shfl_xor_sync(0xffffffffu, rmax0, 1));
            rmax0 = fmaxf(rmax0, __shfl_xor_sync(0xffffffffu, rmax0, 2));
            rmax1 = fmaxf(rmax1, __shfl_xor_sync(0xffffffffu, rmax1, 1));
            rmax1 = fmaxf(rmax1, __shfl_xor_sync(0xffffffffu, rmax1, 2));

            float mnew0 = fmaxf(mrun0, rmax0);
            float mnew1 = fmaxf(mrun1, rmax1);
            float corr0 = __expf(mrun0 - mnew0);
            float corr1 = __expf(mrun1 - mnew1);

            float p[4][4];
            float ls0 = 0.f, ls1 = 0.f;
#pragma unroll
            for (int nf = 0; nf < 4; nf++) {
                p[nf][0] = __expf(sc[nf][0] - mnew0);
                p[nf][1] = __expf(sc[nf][1] - mnew0);
                p[nf][2] = __expf(sc[nf][2] - mnew1);
                p[nf][3] = __expf(sc[nf][3] - mnew1);
                ls0 += p[nf][0] + p[nf][1];
                ls1 += p[nf][2] + p[nf][3];
            }
            ls0 += __shfl_xor_sync(0xffffffffu, ls0, 1);
            ls0 += __shfl_xor_sync(0xffffffffu, ls0, 2);
            ls1 += __shfl_xor_sync(0xffffffffu, ls1, 1);
            ls1 += __shfl_xor_sync(0xffffffffu, ls1, 2);
            lrun0 = lrun0 * corr0 + ls0;
            lrun1 = lrun1 * corr1 + ls1;

            // rescale running output
#pragma unroll
            for (int nf = 0; nf < 8; nf++) {
                o[nf][0] *= corr0; o[nf][1] *= corr0;
                o[nf][2] *= corr1; o[nf][3] *= corr1;
            }

            // P fragments (hi/lo) directly from registers
            uint32_t pfh[2][4], pfl[2][4];
#pragma unroll
            for (int kc2 = 0; kc2 < 2; kc2++) {
                const float* pa = p[2 * kc2];
                const float* pb = p[2 * kc2 + 1];
                float v0, v1, h0f, h1f;
#pragma unroll
                for (int e = 0; e < 4; e++) {
                    const float* src = (e & 2) ? pb : pa;
                    v0 = (e & 1) ? src[2] : src[0];
                    v1 = (e & 1) ? src[3] : src[1];
                    pfh[kc2][e] = pack_bf2(v0, v1);
                    __nv_bfloat162 hp = *(__nv_bfloat162*)&pfh[kc2][e];
                    h0f = __bfloat162float(hp.x);
                    h1f = __bfloat162float(hp.y);
                    pfl[kc2][e] = pack_bf2(v0 - h0f, v1 - h1f);
                }
            }

            // --- PV: o += P[16x32] @ V[32x64] (bf16x3) ---
#pragma unroll
            for (int kc2 = 0; kc2 < 2; kc2++) {
#pragma unroll
                for (int nf = 0; nf < 8; nf++) {
                    const bf16* vh_ = &sVh[buf][nf * 8 + g][kc2 * 16 + 2 * t];
                    const bf16* vl_ = &sVl[buf][nf * 8 + g][kc2 * 16 + 2 * t];
                    uint32_t Bh2[2] = { *(const uint32_t*)vh_,
                                        *(const uint32_t*)(vh_ + 8) };
                    uint32_t Bl2[2] = { *(const uint32_t*)vl_,
                                        *(const uint32_t*)(vl_ + 8) };
                    mma16816(o[nf], pfh[kc2], Bh2);
                    mma16816(o[nf], pfh[kc2], Bl2);
                    mma16816(o[nf], pfl[kc2], Bh2);
                }
            }
            mrun0 = mnew0;
            mrun1 = mnew1;
        }

        // --- epilogue: ctx = o / lsum, bf16 hi/lo, [B,S,H*dh] ---
        float inv0 = 1.f / lrun0, inv1 = 1.f / lrun1;
        long base0 = ((long)(b * SS + r0) * HH + h) * DH;
        long base1 = ((long)(b * SS + r1) * HH + h) * DH;
#pragma unroll
        for (int nf = 0; nf < 8; nf++) {
            int d = nf * 8 + 2 * t;
            float x0 = o[nf][0] * inv0, x1 = o[nf][1] * inv0;
            float x2 = o[nf][2] * inv1, x3 = o[nf][3] * inv1;
            uint32_t h01 = pack_bf2(x0, x1);
            uint32_t h23 = pack_bf2(x2, x3);
            __nv_bfloat162 hp0 = *(__nv_bfloat162*)&h01;
            __nv_bfloat162 hp1 = *(__nv_bfloat162*)&h23;
            uint32_t l01 = pack_bf2(x0 - __bfloat162float(hp0.x),
                                    x1 - __bfloat162float(hp0.y));
            uint32_t l23 = pack_bf2(x2 - __bfloat162float(hp1.x),
                                    x3 - __bfloat162float(hp1.y));
            *(uint32_t*)(Ch + base0 + d) = h01;
            *(uint32_t*)(Cl + base0 + d) = l01;
            *(uint32_t*)(Ch + base1 + d) = h23;
            *(uint32_t*)(Cl + base1 + d) = l23;
        }
    }
}

// ---------------------------------------------------------------------------
extern "C" void kernel_launch(void* const* d_in, const int* in_sizes, int n_in,
                              void* d_out, int out_size)
{
    (void)in_sizes; (void)n_in; (void)out_size;
    const float* x   = (const float*)d_in[0];
    const int*   pos = (const int*)  d_in[1];
    const float* w[4] = { (const float*)d_in[2], (const float*)d_in[3],
                          (const float*)d_in[4], (const float*)d_in[5] };
    float* out = (float*)d_out;

    bf16 *qh, *ql, *kh, *kl, *vh, *vl, *xh, *xl, *ch, *cl, *wh, *wl;
    cudaGetSymbolAddress((void**)&qh, g_qh);
    cudaGetSymbolAddress((void**)&ql, g_ql);
    cudaGetSymbolAddress((void**)&kh, g_kh);
    cudaGetSymbolAddress((void**)&kl, g_kl);
    cudaGetSymbolAddress((void**)&vh, g_vh);
    cudaGetSymbolAddress((void**)&vl, g_vl);
    cudaGetSymbolAddress((void**)&xh, g_xh);
    cudaGetSymbolAddress((void**)&xl, g_xl);
    cudaGetSymbolAddress((void**)&ch, g_ch);
    cudaGetSymbolAddress((void**)&cl, g_cl);
    cudaGetSymbolAddress((void**)&wh, g_wh);
    cudaGetSymbolAddress((void**)&wl, g_wl);

    // fp32 -> bf16 hi/lo splits (input + weights)
    const int nX4 = BB * SS * DD / 4;
    split_kernel<<<(nX4 + 255) / 256, 256>>>(x, xh, xl, nX4);
    const int nW4 = DD * DD / 4;
    for (int i = 0; i < 4; i++)
        split_kernel<<<(nW4 + 255) / 256, 256>>>(w[i], wh + (size_t)i * DD * DD,
                                                 wl + (size_t)i * DD * DD, nW4);

    dim3 gg(DD / 128, (BB * SS) / 128);   // 8 x 64
    gemm_mma<<<gg, 256, GSMEM>>>(xh, xl, wh + 0 * (size_t)DD * DD,
                                 wl + 0 * (size_t)DD * DD,
                                 nullptr, qh, ql, pos, 2);   // Q + RoPE
    gemm_mma<<<gg, 256, GSMEM>>>(xh, xl, wh + 1 * (size_t)DD * DD,
                                 wl + 1 * (size_t)DD * DD,
                                 nullptr, kh, kl, pos, 2);   // K + RoPE
    gemm_mma<<<gg, 256, GSMEM>>>(xh, xl, wh + 2 * (size_t)DD * DD,
                                 wl + 2 * (size_t)DD * DD,
                                 nullptr, vh, vl, pos, 1);   // V

    dim3 ga(16, BB * HH);                 // paired causal q-tiles (qi, 31-qi)
    attn_mma<<<ga, 128>>>(qh, ql, kh, kl, vh, vl, ch, cl);

    gemm_mma<<<gg, 256, GSMEM>>>(ch, cl, wh + 3 * (size_t)DD * DD,
                                 wl + 3 * (size_t)DD * DD,
                                 out, nullptr, nullptr, pos, 0);  // Wo
}

// round 12
// speedup vs baseline: 3.9994x; 1.1220x over previous
#include <cuda_runtime.h>
#include <cuda_bf16.h>
#include <math.h>
#include <stdint.h>

#define BB 4
#define SS 2048
#define DD 1024
#define HH 16
#define DH 64
#define KDIM 1024

typedef __nv_bfloat16 bf16;

// ---------------- device scratch (allocation-free rule) ----------------
__device__ bf16 g_qh[BB * HH * SS * DH];   // Q RoPE'd, head-major, hi/lo
__device__ bf16 g_ql[BB * HH * SS * DH];
__device__ bf16 g_kh[BB * HH * SS * DH];
__device__ bf16 g_kl[BB * HH * SS * DH];
__device__ bf16 g_vh[BB * HH * SS * DH];
__device__ bf16 g_vl[BB * HH * SS * DH];
__device__ bf16 g_xh[BB * SS * DD];        // input hi/lo split
__device__ bf16 g_xl[BB * SS * DD];
__device__ bf16 g_ch[BB * SS * DD];        // attention ctx hi/lo
__device__ bf16 g_cl[BB * SS * DD];
__device__ bf16 g_wh[4][DD * DD];          // wq,wk,wv,wo hi
__device__ bf16 g_wl[4][DD * DD];          // lo

// ---------------------------------------------------------------------------
__device__ __forceinline__ void mma16816(float* c, const uint32_t* a,
                                         const uint32_t* b) {
    asm volatile(
        "mma.sync.aligned.m16n8k16.row.col.f32.bf16.bf16.f32 "
        "{%0,%1,%2,%3}, {%4,%5,%6,%7}, {%8,%9}, {%0,%1,%2,%3};"
        : "+f"(c[0]), "+f"(c[1]), "+f"(c[2]), "+f"(c[3])
        : "r"(a[0]), "r"(a[1]), "r"(a[2]), "r"(a[3]), "r"(b[0]), "r"(b[1]));
}
__device__ __forceinline__ void ldsm_x4(uint32_t* r, uint32_t saddr) {
    asm volatile("ldmatrix.sync.aligned.m8n8.x4.shared.b16 {%0,%1,%2,%3}, [%4];"
                 : "=r"(r[0]), "=r"(r[1]), "=r"(r[2]), "=r"(r[3]) : "r"(saddr));
}
__device__ __forceinline__ void cp16(uint32_t sdst, const void* gsrc) {
    asm volatile("cp.async.cg.shared.global [%0], [%1], 16;"
                 :: "r"(sdst), "l"(gsrc));
}
#define CP_COMMIT() asm volatile("cp.async.commit_group;" ::: "memory")
#define CP_WAIT1()  asm volatile("cp.async.wait_group 1;" ::: "memory")
#define CP_WAIT0()  asm volatile("cp.async.wait_group 0;" ::: "memory")

__device__ __forceinline__ uint32_t pack_bf2(float lo, float hi) {
    __nv_bfloat162 t = __floats2bfloat162_rn(lo, hi);
    return *(uint32_t*)&t;
}

// ---------------------------------------------------------------------------
// fp32 -> (hi, lo) bf16 split, vectorized by 4
// ---------------------------------------------------------------------------
__global__ void split_kernel(const float* __restrict__ s,
                             bf16* __restrict__ hi, bf16* __restrict__ lo,
                             int n4) {
    int i = blockIdx.x * blockDim.x + threadIdx.x;
    if (i >= n4) return;
    float4 v = ((const float4*)s)[i];
    bf16 h0 = __float2bfloat16(v.x), h1 = __float2bfloat16(v.y);
    bf16 h2 = __float2bfloat16(v.z), h3 = __float2bfloat16(v.w);
    bf16 l0 = __float2bfloat16(v.x - __bfloat162float(h0));
    bf16 l1 = __float2bfloat16(v.y - __bfloat162float(h1));
    bf16 l2 = __float2bfloat16(v.z - __bfloat162float(h2));
    bf16 l3 = __float2bfloat16(v.w - __bfloat162float(h3));
    ((__nv_bfloat162*)hi)[2 * i]     = __halves2bfloat162(h0, h1);
    ((__nv_bfloat162*)hi)[2 * i + 1] = __halves2bfloat162(h2, h3);
    ((__nv_bfloat162*)lo)[2 * i]     = __halves2bfloat162(l0, l1);
    ((__nv_bfloat162*)lo)[2 * i + 1] = __halves2bfloat162(l2, l3);
}

// ---------------------------------------------------------------------------
// mma.sync bf16x3 GEMM: Y = A[M,K] @ W[N,K]^T.  CTA 128x128, 8 warps 64x32.
// Double-buffered cp.async pipeline (2-deep) + ldmatrix fragment loads.
// epi: 0 = fp32 row-major, 1 = bf16 hi/lo head-major, 2 = +fused RoPE
// ---------------------------------------------------------------------------
#define SROW 80                       // bytes per smem row (32 bf16 + pad)
#define STILE (128 * SROW)            // 10240 B per array tile
#define SBUF  (4 * STILE)             // 40960 B per pipeline stage
#define GSMEM (2 * SBUF)              // 81920 B total
#define NCHUNK (KDIM / 32)            // 32

__global__ void __launch_bounds__(256) gemm_mma(
    const bf16* __restrict__ ah, const bf16* __restrict__ al,
    const bf16* __restrict__ wh, const bf16* __restrict__ wl,
    float* __restrict__ Y, bf16* __restrict__ Yh, bf16* __restrict__ Yl,
    const int* __restrict__ pos, int epi)
{
    extern __shared__ char smc[];
    const uint32_t sbase = (uint32_t)__cvta_generic_to_shared(smc);

    const int tid = threadIdx.x;
    const int w = tid >> 5, l = tid & 31;
    const int g = l >> 2, t = l & 3;
    const int wm = (w & 1) * 64, wn = (w >> 1) * 32;
    const int bm = blockIdx.y * 128, bn = blockIdx.x * 128;

    // loader mapping: 2 threads per row, each 32 B (16 bf16)
    const int lr = tid >> 1, chf = tid & 1;
    const long arow = (long)(bm + lr) * KDIM + chf * 16;
    const long wrow = (long)(bn + lr) * KDIM + chf * 16;
    const uint32_t soff = (uint32_t)(lr * SROW + chf * 32);

    // ldmatrix lane offsets (match proven scalar fragment mapping)
    const uint32_t offA0 = (uint32_t)((wm + (l & 15)) * SROW +
                                      ((l & 16) ? 16 : 0));
    const uint32_t offB0 = (uint32_t)((wn + (l & 7) + ((l & 16) ? 8 : 0)) * SROW +
                                      ((l & 8) ? 16 : 0));

    float acc[4][4][4];
#pragma unroll
    for (int mt = 0; mt < 4; mt++)
#pragma unroll
        for (int nt = 0; nt < 4; nt++)
#pragma unroll
            for (int e = 0; e < 4; e++) acc[mt][nt][e] = 0.f;

    // prefetch helper (lambda-free, inlined twice)
#define PREFETCH(SB, K0)                                                \
    do {                                                                \
        cp16((SB) + soff,                  ah + arow + (K0));           \
        cp16((SB) + soff + 16,             ah + arow + (K0) + 8);       \
        cp16((SB) + STILE + soff,          al + arow + (K0));           \
        cp16((SB) + STILE + soff + 16,     al + arow + (K0) + 8);       \
        cp16((SB) + 2 * STILE + soff,      wh + wrow + (K0));           \
        cp16((SB) + 2 * STILE + soff + 16, wh + wrow + (K0) + 8);       \
        cp16((SB) + 3 * STILE + soff,      wl + wrow + (K0));           \
        cp16((SB) + 3 * STILE + soff + 16, wl + wrow + (K0) + 8);       \
    } while (0)

    PREFETCH(sbase, 0);
    CP_COMMIT();
    PREFETCH(sbase + SBUF, 32);
    CP_COMMIT();

    for (int ck = 0; ck < NCHUNK; ck++) {
        if (ck == NCHUNK - 1) CP_WAIT0(); else CP_WAIT1();
        __syncthreads();

        const uint32_t sbuf = sbase + (uint32_t)(ck & 1) * SBUF;
#pragma unroll
        for (int ks = 0; ks < 2; ks++) {
            const uint32_t kb = ks * 32;
            uint32_t Bh4[2][4], Bl4[2][4];
#pragma unroll
            for (int np = 0; np < 2; np++) {
                uint32_t ob = offB0 + np * 16 * SROW + kb;
                ldsm_x4(Bh4[np], sbuf + 2 * STILE + ob);
                ldsm_x4(Bl4[np], sbuf + 3 * STILE + ob);
            }
#pragma unroll
            for (int mt = 0; mt < 4; mt++) {
                uint32_t oa = offA0 + mt * 16 * SROW + kb;
                uint32_t Ah4[4], Al4[4];
                ldsm_x4(Ah4, sbuf + oa);
                ldsm_x4(Al4, sbuf + STILE + oa);
#pragma unroll
                for (int nt = 0; nt < 4; nt++) {
                    const uint32_t* Bh2 = &Bh4[nt >> 1][(nt & 1) * 2];
                    const uint32_t* Bl2 = &Bl4[nt >> 1][(nt & 1) * 2];
                    mma16816(acc[mt][nt], Ah4, Bh2);
                    mma16816(acc[mt][nt], Ah4, Bl2);
                    mma16816(acc[mt][nt], Al4, Bh2);
                }
            }
        }
        __syncthreads();
        if (ck + 2 < NCHUNK) {
            PREFETCH(sbase + (uint32_t)(ck & 1) * SBUF, (ck + 2) * 32);
            CP_COMMIT();
        }
    }
#undef PREFETCH

    // epilogue: lane holds rows {m0, m0+8}, cols {n, n+1} per fragment
#pragma unroll
    for (int mt = 0; mt < 4; mt++) {
        const int m0 = bm + wm + mt * 16 + g;
#pragma unroll
        for (int nt = 0; nt < 4; nt++) {
            const int n = bn + wn + nt * 8 + t * 2;   // even
            float c0 = acc[mt][nt][0], c1 = acc[mt][nt][1];
            float c2 = acc[mt][nt][2], c3 = acc[mt][nt][3];
            if (epi == 0) {
                *(float2*)(Y + (long)m0 * DD + n)       = make_float2(c0, c1);
                *(float2*)(Y + (long)(m0 + 8) * DD + n) = make_float2(c2, c3);
            } else {
                const int h = n >> 6, d = n & 63;      // d even
#pragma unroll
                for (int half = 0; half < 2; half++) {
                    int m  = m0 + half * 8;
                    int bq = m >> 11, sq = m & 2047;
                    float x1 = half ? c2 : c0;
                    float x2 = half ? c3 : c1;
                    if (epi == 2) {
                        float fr  = powf(10000.f, -(float)(d >> 1) * (1.f / 32.f));
                        float ang = (float)pos[sq] * fr;
                        float cc = cosf(ang), sn = sinf(ang);
                        float o1 = x1 * cc - x2 * sn;
                        float o2 = x1 * sn + x2 * cc;
                        x1 = o1; x2 = o2;
                    }
                    long idx = ((long)(bq * HH + h) * SS + sq) * DH + d;
                    bf16 h1 = __float2bfloat16(x1);
                    bf16 h2 = __float2bfloat16(x2);
                    __nv_bfloat162 hp = __halves2bfloat162(h1, h2);
                    *(uint32_t*)(Yh + idx) = *(uint32_t*)&hp;
                    bf16 l1 = __float2bfloat16(x1 - __bfloat162float(h1));
                    bf16 l2 = __float2bfloat16(x2 - __bfloat162float(h2));
                    __nv_bfloat162 lp = __halves2bfloat162(l1, l2);
                    *(uint32_t*)(Yl + idx) = *(uint32_t*)&lp;
                }
            }
        }
    }
}

// ---------------------------------------------------------------------------
// MMA flash attention (unchanged from round 10 -- proven).
// CTA = 64 q rows (4 warps x 16), k-tile = 32 keys, bf16x3 QK^T and PV,
// paired causal q-tiles (qi, 31-qi).
// ---------------------------------------------------------------------------
__global__ void __launch_bounds__(128) attn_mma(
    const bf16* __restrict__ Qh, const bf16* __restrict__ Ql,
    const bf16* __restrict__ Kh, const bf16* __restrict__ Kl,
    const bf16* __restrict__ Vh, const bf16* __restrict__ Vl,
    bf16* __restrict__ Ch, bf16* __restrict__ Cl)
{
    __shared__ __align__(16) bf16 sKh[2][32][72];
    __shared__ __align__(16) bf16 sKl[2][32][72];
    __shared__ __align__(16) bf16 sVh[2][64][40];   // transposed [d][key]
    __shared__ __align__(16) bf16 sVl[2][64][40];

    const int tid = threadIdx.x;
    const int w = tid >> 5, l = tid & 31;
    const int g = l >> 2, t = l & 3;
    const int bh = blockIdx.y, b = bh >> 4, h = bh & 15;
    const long hoff = (long)bh * SS * DH;

    const int krow = tid >> 2, kseg = tid & 3;
    const int vkp = tid & 15, vdc = tid >> 4;
    const float scale = 0.125f;

    for (int sel = 0; sel < 2; sel++) {
        const int qi = sel ? 31 - (int)blockIdx.x : (int)blockIdx.x;
        const int q0 = qi * 64;
        const int r0 = q0 + w * 16 + g;
        const int r1 = r0 + 8;

        uint32_t qfh[4][4], qfl[4][4];
        {
            const bf16* p0h = Qh + hoff + (long)r0 * DH;
            const bf16* p1h = Qh + hoff + (long)r1 * DH;
            const bf16* p0l = Ql + hoff + (long)r0 * DH;
            const bf16* p1l = Ql + hoff + (long)r1 * DH;
#pragma unroll
            for (int kc = 0; kc < 4; kc++) {
                int o0 = kc * 16 + 2 * t;
                qfh[kc][0] = *(const uint32_t*)(p0h + o0);
                qfh[kc][1] = *(const uint32_t*)(p1h + o0);
                qfh[kc][2] = *(const uint32_t*)(p0h + o0 + 8);
                qfh[kc][3] = *(const uint32_t*)(p1h + o0 + 8);
                qfl[kc][0] = *(const uint32_t*)(p0l + o0);
                qfl[kc][1] = *(const uint32_t*)(p1l + o0);
                qfl[kc][2] = *(const uint32_t*)(p0l + o0 + 8);
                qfl[kc][3] = *(const uint32_t*)(p1l + o0 + 8);
            }
        }

        float o[8][4];
#pragma unroll
        for (int nf = 0; nf < 8; nf++)
#pragma unroll
            for (int e = 0; e < 4; e++) o[nf][e] = 0.f;
        float mrun0 = -INFINITY, mrun1 = -INFINITY;
        float lrun0 = 0.f, lrun1 = 0.f;

        const int ktiles = 2 * qi + 2;
        for (int kt = 0; kt < ktiles; kt++) {
            const int k0 = kt * 32;
            const int buf = kt & 1;

            {
                const float4* sh = (const float4*)(Kh + hoff +
                                   (long)(k0 + krow) * DH + kseg * 16);
                const float4* sl = (const float4*)(Kl + hoff +
                                   (long)(k0 + krow) * DH + kseg * 16);
                *(float4*)&sKh[buf][krow][kseg * 16]     = sh[0];
                *(float4*)&sKh[buf][krow][kseg * 16 + 8] = sh[1];
                *(float4*)&sKl[buf][krow][kseg * 16]     = sl[0];
                *(float4*)&sKl[buf][krow][kseg * 16 + 8] = sl[1];
            }
            {
                const uint32_t* r0h = (const uint32_t*)(Vh + hoff +
                                      (long)(k0 + 2 * vkp) * DH + vdc * 8);
                const uint32_t* r1h = (const uint32_t*)(Vh + hoff +
                                      (long)(k0 + 2 * vkp + 1) * DH + vdc * 8);
                const uint32_t* r0l = (const uint32_t*)(Vl + hoff +
                                      (long)(k0 + 2 * vkp) * DH + vdc * 8);
                const uint32_t* r1l = (const uint32_t*)(Vl + hoff +
                                      (long)(k0 + 2 * vkp + 1) * DH + vdc * 8);
#pragma unroll
                for (int m = 0; m < 4; m++) {
                    uint32_t ah_ = r0h[m], bh_ = r1h[m];
                    uint32_t al_ = r0l[m], bl_ = r1l[m];
                    int d0 = vdc * 8 + 2 * m;
                    *(uint32_t*)&sVh[buf][d0][2 * vkp]     = __byte_perm(ah_, bh_, 0x5410);
                    *(uint32_t*)&sVh[buf][d0 + 1][2 * vkp] = __byte_perm(ah_, bh_, 0x7632);
                    *(uint32_t*)&sVl[buf][d0][2 * vkp]     = __byte_perm(al_, bl_, 0x5410);
                    *(uint32_t*)&sVl[buf][d0 + 1][2 * vkp] = __byte_perm(al_, bl_, 0x7632);
                }
            }
            __syncthreads();

            float sc[4][4];
#pragma unroll
            for (int nf = 0; nf < 4; nf++) {
#pragma unroll
                for (int e = 0; e < 4; e++) sc[nf][e] = 0.f;
#pragma unroll
                for (int kc = 0; kc < 4; kc++) {
                    const bf16* kh_ = &sKh[buf][nf * 8 + g][kc * 16 + 2 * t];
                    const bf16* kl_ = &sKl[buf][nf * 8 + g][kc * 16 + 2 * t];
                    uint32_t Bh2[2] = { *(const uint32_t*)kh_,
                                        *(const uint32_t*)(kh_ + 8) };
                    uint32_t Bl2[2] = { *(const uint32_t*)kl_,
                                        *(const uint32_t*)(kl_ + 8) };
                    mma16816(sc[nf], qfh[kc], Bh2);
                    mma16816(sc[nf], qfh[kc], Bl2);
                    mma16816(sc[nf], qfl[kc], Bh2);
                }
            }
            float rmax0 = -INFINITY, rmax1 = -INFINITY;
#pragma unroll
            for (int nf = 0; nf < 4; nf++) {
                int cb = k0 + nf * 8 + 2 * t;
                sc[nf][0] = (cb     <= r0) ? sc[nf][0] * scale : -INFINITY;
                sc[nf][1] = (cb + 1 <= r0) ? sc[nf][1] * scale : -INFINITY;
                sc[nf][2] = (cb     <= r1) ? sc[nf][2] * scale : -INFINITY;
                sc[nf][3] = (cb + 1 <= r1) ? sc[nf][3] * scale : -INFINITY;
                rmax0 = fmaxf(rmax0, fmaxf(sc[nf][0], sc[nf][1]));
                rmax1 = fmaxf(rmax1, fmaxf(sc[nf][2], sc[nf][3]));
            }
            rmax0 = fmaxf(rmax0, __shfl_xor_sync(0xffffffffu, rmax0, 1));
            rmax0 = fmaxf(rmax0, __shfl_xor_sync(0xffffffffu, rmax0, 2));
            rmax1 = fmaxf(rmax1, __shfl_xor_sync(0xffffffffu, rmax1, 1));
            rmax1 = fmaxf(rmax1, __shfl_xor_sync(0xffffffffu, rmax1, 2));

            float mnew0 = fmaxf(mrun0, rmax0);
            float mnew1 = fmaxf(mrun1, rmax1);
            float corr0 = __expf(mrun0 - mnew0);
            float corr1 = __expf(mrun1 - mnew1);

            float p[4][4];
            float ls0 = 0.f, ls1 = 0.f;
#pragma unroll
            for (int nf = 0; nf < 4; nf++) {
                p[nf][0] = __expf(sc[nf][0] - mnew0);
                p[nf][1] = __expf(sc[nf][1] - mnew0);
                p[nf][2] = __expf(sc[nf][2] - mnew1);
                p[nf][3] = __expf(sc[nf][3] - mnew1);
                ls0 += p[nf][0] + p[nf][1];
                ls1 += p[nf][2] + p[nf][3];
            }
            ls0 += __shfl_xor_sync(0xffffffffu, ls0, 1);
            ls0 += __shfl_xor_sync(0xffffffffu, ls0, 2);
            ls1 += __shfl_xor_sync(0xffffffffu, ls1, 1);
            ls1 += __shfl_xor_sync(0xffffffffu, ls1, 2);
            lrun0 = lrun0 * corr0 + ls0;
            lrun1 = lrun1 * corr1 + ls1;

#pragma unroll
            for (int nf = 0; nf < 8; nf++) {
                o[nf][0] *= corr0; o[nf][1] *= corr0;
                o[nf][2] *= corr1; o[nf][3] *= corr1;
            }

            uint32_t pfh[2][4], pfl[2][4];
#pragma unroll
            for (int kc2 = 0; kc2 < 2; kc2++) {
                const float* pa = p[2 * kc2];
                const float* pb = p[2 * kc2 + 1];
                float v0, v1, h0f, h1f;
#pragma unroll
                for (int e = 0; e < 4; e++) {
                    const float* src = (e & 2) ? pb : pa;
                    v0 = (e & 1) ? src[2] : src[0];
                    v1 = (e & 1) ? src[3] : src[1];
                    pfh[kc2][e] = pack_bf2(v0, v1);
                    __nv_bfloat162 hp = *(__nv_bfloat162*)&pfh[kc2][e];
                    h0f = __bfloat162float(hp.x);
                    h1f = __bfloat162float(hp.y);
                    pfl[kc2][e] = pack_bf2(v0 - h0f, v1 - h1f);
                }
            }

#pragma unroll
            for (int kc2 = 0; kc2 < 2; kc2++) {
#pragma unroll
                for (int nf = 0; nf < 8; nf++) {
                    const bf16* vh_ = &sVh[buf][nf * 8 + g][kc2 * 16 + 2 * t];
                    const bf16* vl_ = &sVl[buf][nf * 8 + g][kc2 * 16 + 2 * t];
                    uint32_t Bh2[2] = { *(const uint32_t*)vh_,
                                        *(const uint32_t*)(vh_ + 8) };
                    uint32_t Bl2[2] = { *(const uint32_t*)vl_,
                                        *(const uint32_t*)(vl_ + 8) };
                    mma16816(o[nf], pfh[kc2], Bh2);
                    mma16816(o[nf], pfh[kc2], Bl2);
                    mma16816(o[nf], pfl[kc2], Bh2);
                }
            }
            mrun0 = mnew0;
            mrun1 = mnew1;
        }

        float inv0 = 1.f / lrun0, inv1 = 1.f / lrun1;
        long base0 = ((long)(b * SS + r0) * HH + h) * DH;
        long base1 = ((long)(b * SS + r1) * HH + h) * DH;
#pragma unroll
        for (int nf = 0; nf < 8; nf++) {
            int d = nf * 8 + 2 * t;
            float x0 = o[nf][0] * inv0, x1 = o[nf][1] * inv0;
            float x2 = o[nf][2] * inv1, x3 = o[nf][3] * inv1;
            uint32_t h01 = pack_bf2(x0, x1);
            uint32_t h23 = pack_bf2(x2, x3);
            __nv_bfloat162 hp0 = *(__nv_bfloat162*)&h01;
            __nv_bfloat162 hp1 = *(__nv_bfloat162*)&h23;
            uint32_t l01 = pack_bf2(x0 - __bfloat162float(hp0.x),
                                    x1 - __bfloat162float(hp0.y));
            uint32_t l23 = pack_bf2(x2 - __bfloat162float(hp1.x),
                                    x3 - __bfloat162float(hp1.y));
            *(uint32_t*)(Ch + base0 + d) = h01;
            *(uint32_t*)(Cl + base0 + d) = l01;
            *(uint32_t*)(Ch + base1 + d) = h23;
            *(uint32_t*)(Cl + base1 + d) = l23;
        }
    }
}

// ---------------------------------------------------------------------------
extern "C" void kernel_launch(void* const* d_in, const int* in_sizes, int n_in,
                              void* d_out, int out_size)
{
    (void)in_sizes; (void)n_in; (void)out_size;
    const float* x   = (const float*)d_in[0];
    const int*   pos = (const int*)  d_in[1];
    const float* w[4] = { (const float*)d_in[2], (const float*)d_in[3],
                          (const float*)d_in[4], (const float*)d_in[5] };
    float* out = (float*)d_out;

    bf16 *qh, *ql, *kh, *kl, *vh, *vl, *xh, *xl, *ch, *cl, *wh, *wl;
    cudaGetSymbolAddress((void**)&qh, g_qh);
    cudaGetSymbolAddress((void**)&ql, g_ql);
    cudaGetSymbolAddress((void**)&kh, g_kh);
    cudaGetSymbolAddress((void**)&kl, g_kl);
    cudaGetSymbolAddress((void**)&vh, g_vh);
    cudaGetSymbolAddress((void**)&vl, g_vl);
    cudaGetSymbolAddress((void**)&xh, g_xh);
    cudaGetSymbolAddress((void**)&xl, g_xl);
    cudaGetSymbolAddress((void**)&ch, g_ch);
    cudaGetSymbolAddress((void**)&cl, g_cl);
    cudaGetSymbolAddress((void**)&wh, g_wh);
    cudaGetSymbolAddress((void**)&wl, g_wl);

    cudaFuncSetAttribute(gemm_mma, cudaFuncAttributeMaxDynamicSharedMemorySize,
                         GSMEM);

    const int nX4 = BB * SS * DD / 4;
    split_kernel<<<(nX4 + 255) / 256, 256>>>(x, xh, xl, nX4);
    const int nW4 = DD * DD / 4;
    for (int i = 0; i < 4; i++)
        split_kernel<<<(nW4 + 255) / 256, 256>>>(w[i], wh + (size_t)i * DD * DD,
                                                 wl + (size_t)i * DD * DD, nW4);

    dim3 gg(DD / 128, (BB * SS) / 128);   // 8 x 64
    gemm_mma<<<gg, 256, GSMEM>>>(xh, xl, wh + 0 * (size_t)DD * DD,
                                 wl + 0 * (size_t)DD * DD,
                                 nullptr, qh, ql, pos, 2);   // Q + RoPE
    gemm_mma<<<gg, 256, GSMEM>>>(xh, xl, wh + 1 * (size_t)DD * DD,
                                 wl + 1 * (size_t)DD * DD,
                                 nullptr, kh, kl, pos, 2);   // K + RoPE
    gemm_mma<<<gg, 256, GSMEM>>>(xh, xl, wh + 2 * (size_t)DD * DD,
                                 wl + 2 * (size_t)DD * DD,
                                 nullptr, vh, vl, pos, 1);   // V

    dim3 ga(16, BB * HH);                 // paired causal q-tiles (qi, 31-qi)
    attn_mma<<<ga, 128>>>(qh, ql, kh, kl, vh, vl, ch, cl);

    gemm_mma<<<gg, 256, GSMEM>>>(ch, cl, wh + 3 * (size_t)DD * DD,
                                 wl + 3 * (size_t)DD * DD,
                                 out, nullptr, nullptr, pos, 0);  // Wo
}

// round 15
// speedup vs baseline: 4.1110x; 1.0279x over previous
#include <cuda_runtime.h>
#include <cuda_bf16.h>
#include <math.h>
#include <stdint.h>

#define BB 4
#define SS 2048
#define DD 1024
#define HH 16
#define DH 64
#define KDIM 1024

typedef __nv_bfloat16 bf16;

// ---------------- device scratch (allocation-free rule) ----------------
__device__ bf16 g_qh[BB * HH * SS * DH];   // Q RoPE'd, head-major, hi/lo
__device__ bf16 g_ql[BB * HH * SS * DH];
__device__ bf16 g_kh[BB * HH * SS * DH];
__device__ bf16 g_kl[BB * HH * SS * DH];
__device__ bf16 g_vh[BB * HH * SS * DH];
__device__ bf16 g_vl[BB * HH * SS * DH];
__device__ bf16 g_xh[BB * SS * DD];        // input hi/lo split
__device__ bf16 g_xl[BB * SS * DD];
__device__ bf16 g_ch[BB * SS * DD];        // attention ctx hi/lo
__device__ bf16 g_cl[BB * SS * DD];
__device__ bf16 g_wh[4][DD * DD];          // wq,wk,wv,wo hi
__device__ bf16 g_wl[4][DD * DD];          // lo

// ---------------------------------------------------------------------------
__device__ __forceinline__ void mma16816(float* c, const uint32_t* a,
                                         const uint32_t* b) {
    asm volatile(
        "mma.sync.aligned.m16n8k16.row.col.f32.bf16.bf16.f32 "
        "{%0,%1,%2,%3}, {%4,%5,%6,%7}, {%8,%9}, {%0,%1,%2,%3};"
        : "+f"(c[0]), "+f"(c[1]), "+f"(c[2]), "+f"(c[3])
        : "r"(a[0]), "r"(a[1]), "r"(a[2]), "r"(a[3]), "r"(b[0]), "r"(b[1]));
}
__device__ __forceinline__ void ldsm_x4(uint32_t* r, uint32_t saddr) {
    asm volatile("ldmatrix.sync.aligned.m8n8.x4.shared.b16 {%0,%1,%2,%3}, [%4];"
                 : "=r"(r[0]), "=r"(r[1]), "=r"(r[2]), "=r"(r[3]) : "r"(saddr));
}
__device__ __forceinline__ void cp16(uint32_t sdst, const void* gsrc) {
    asm volatile("cp.async.cg.shared.global [%0], [%1], 16;"
                 :: "r"(sdst), "l"(gsrc));
}
#define CP_COMMIT() asm volatile("cp.async.commit_group;" ::: "memory")
#define CP_WAIT2()  asm volatile("cp.async.wait_group 2;" ::: "memory")

__device__ __forceinline__ uint32_t pack_bf2(float lo, float hi) {
    __nv_bfloat162 t = __floats2bfloat162_rn(lo, hi);
    return *(uint32_t*)&t;
}

// ---------------------------------------------------------------------------
// fp32 -> (hi, lo) bf16 split, vectorized by 4
// ---------------------------------------------------------------------------
__global__ void split_kernel(const float* __restrict__ s,
                             bf16* __restrict__ hi, bf16* __restrict__ lo,
                             int n4) {
    int i = blockIdx.x * blockDim.x + threadIdx.x;
    if (i >= n4) return;
    float4 v = ((const float4*)s)[i];
    bf16 h0 = __float2bfloat16(v.x), h1 = __float2bfloat16(v.y);
    bf16 h2 = __float2bfloat16(v.z), h3 = __float2bfloat16(v.w);
    bf16 l0 = __float2bfloat16(v.x - __bfloat162float(h0));
    bf16 l1 = __float2bfloat16(v.y - __bfloat162float(h1));
    bf16 l2 = __float2bfloat16(v.z - __bfloat162float(h2));
    bf16 l3 = __float2bfloat16(v.w - __bfloat162float(h3));
    ((__nv_bfloat162*)hi)[2 * i]     = __halves2bfloat162(h0, h1);
    ((__nv_bfloat162*)hi)[2 * i + 1] = __halves2bfloat162(h2, h3);
    ((__nv_bfloat162*)lo)[2 * i]     = __halves2bfloat162(l0, l1);
    ((__nv_bfloat162*)lo)[2 * i + 1] = __halves2bfloat162(l2, l3);
}

// ---------------------------------------------------------------------------
// mma.sync bf16x3 GEMM: Y = A[M,K] @ W[N,K]^T.  CTA 128x128.
// 512 threads / 16 warps (4m x 4n), warp tile 32x32 -> 32 acc regs/thread,
// ~110 regs total => 4 warps/SMSP resident (2x round-11 latency hiding).
// 4-stage cp.async pipeline, 3-deep prefetch; ldmatrix fragment loads
// (offsets identical to the round-11 proven mapping).
// epi: 0 = fp32 row-major, 1 = bf16 hi/lo head-major, 2 = +fused RoPE
// ---------------------------------------------------------------------------
#define SROW 80                       // bytes per smem row (32 bf16 + pad)
#define STILE (128 * SROW)            // 10240 B per array tile
#define SBUF  (4 * STILE)             // 40960 B per pipeline stage
#define NSTAGE 4
#define GSMEM (NSTAGE * SBUF)         // 163840 B
#define NCHUNK (KDIM / 32)            // 32

__global__ void __launch_bounds__(512) gemm_mma(
    const bf16* __restrict__ ah, const bf16* __restrict__ al,
    const bf16* __restrict__ wh, const bf16* __restrict__ wl,
    float* __restrict__ Y, bf16* __restrict__ Yh, bf16* __restrict__ Yl,
    const int* __restrict__ pos, int epi)
{
    extern __shared__ char smc[];
    const uint32_t sbase = (uint32_t)__cvta_generic_to_shared(smc);

    const int tid = threadIdx.x;
    const int w = tid >> 5, l = tid & 31;
    const int g = l >> 2, t = l & 3;
    const int wm = (w & 3) * 32, wn = (w >> 2) * 32;
    const int bm = blockIdx.y * 128, bn = blockIdx.x * 128;

    // loader mapping: 4 threads per row, each 16 B (8 bf16) per array
    const int lr = tid >> 2, seg = tid & 3;
    const long arow = (long)(bm + lr) * KDIM + seg * 8;
    const long wrow = (long)(bn + lr) * KDIM + seg * 8;
    const uint32_t soff = (uint32_t)(lr * SROW + seg * 16);

    // ldmatrix lane offsets (proven round-11 mapping)
    const uint32_t offA0 = (uint32_t)((wm + (l & 15)) * SROW +
                                      ((l & 16) ? 16 : 0));
    const uint32_t offB0 = (uint32_t)((wn + (l & 7) + ((l & 16) ? 8 : 0)) * SROW +
                                      ((l & 8) ? 16 : 0));

    float acc[2][4][4];
#pragma unroll
    for (int mt = 0; mt < 2; mt++)
#pragma unroll
        for (int nt = 0; nt < 4; nt++)
#pragma unroll
            for (int e = 0; e < 4; e++) acc[mt][nt][e] = 0.f;

#define PREFETCH(SB, K0)                                                \
    do {                                                                \
        cp16((SB) + soff,              ah + arow + (K0));               \
        cp16((SB) + STILE + soff,      al + arow + (K0));               \
        cp16((SB) + 2 * STILE + soff,  wh + wrow + (K0));               \
        cp16((SB) + 3 * STILE + soff,  wl + wrow + (K0));               \
    } while (0)

    PREFETCH(sbase, 0);                 CP_COMMIT();
    PREFETCH(sbase + SBUF, 32);         CP_COMMIT();
    PREFETCH(sbase + 2 * SBUF, 64);     CP_COMMIT();

    for (int ck = 0; ck < NCHUNK; ck++) {
        CP_WAIT2();                      // group for chunk ck complete
        __syncthreads();

        const uint32_t sbuf = sbase + (uint32_t)(ck & 3) * SBUF;
#pragma unroll
        for (int ks = 0; ks < 2; ks++) {
            const uint32_t kb = ks * 32;
            uint32_t Bh4[2][4], Bl4[2][4];
#pragma unroll
            for (int np = 0; np < 2; np++) {
                uint32_t ob = offB0 + np * 16 * SROW + kb;
                ldsm_x4(Bh4[np], sbuf + 2 * STILE + ob);
                ldsm_x4(Bl4[np], sbuf + 3 * STILE + ob);
            }
#pragma unroll
            for (int mt = 0; mt < 2; mt++) {
                uint32_t oa = offA0 + mt * 16 * SROW + kb;
                uint32_t Ah4[4], Al4[4];
                ldsm_x4(Ah4, sbuf + oa);
                ldsm_x4(Al4, sbuf + STILE + oa);
#pragma unroll
                for (int nt = 0; nt < 4; nt++) {
                    const uint32_t* Bh2 = &Bh4[nt >> 1][(nt & 1) * 2];
                    const uint32_t* Bl2 = &Bl4[nt >> 1][(nt & 1) * 2];
                    mma16816(acc[mt][nt], Ah4, Bh2);
                    mma16816(acc[mt][nt], Ah4, Bl2);
                    mma16816(acc[mt][nt], Al4, Bh2);
                }
            }
        }
        if (ck + 3 < NCHUNK)
            PREFETCH(sbase + (uint32_t)((ck + 3) & 3) * SBUF, (ck + 3) * 32);
        CP_COMMIT();                     // unconditional: keeps group count uniform
    }
#undef PREFETCH

    // epilogue: lane holds rows {m0, m0+8}, cols {n, n+1} per fragment
#pragma unroll
    for (int mt = 0; mt < 2; mt++) {
        const int m0 = bm + wm + mt * 16 + g;
#pragma unroll
        for (int nt = 0; nt < 4; nt++) {
            const int n = bn + wn + nt * 8 + t * 2;   // even
            float c0 = acc[mt][nt][0], c1 = acc[mt][nt][1];
            float c2 = acc[mt][nt][2], c3 = acc[mt][nt][3];
            if (epi == 0) {
                *(float2*)(Y + (long)m0 * DD + n)       = make_float2(c0, c1);
                *(float2*)(Y + (long)(m0 + 8) * DD + n) = make_float2(c2, c3);
            } else {
                const int h = n >> 6, d = n & 63;      // d even
#pragma unroll
                for (int half = 0; half < 2; half++) {
                    int m  = m0 + half * 8;
                    int bq = m >> 11, sq = m & 2047;
                    float x1 = half ? c2 : c0;
                    float x2 = half ? c3 : c1;
                    if (epi == 2) {
                        float fr  = powf(10000.f, -(float)(d >> 1) * (1.f / 32.f));
                        float ang = (float)pos[sq] * fr;
                        float cc = cosf(ang), sn = sinf(ang);
                        float o1 = x1 * cc - x2 * sn;
                        float o2 = x1 * sn + x2 * cc;
                        x1 = o1; x2 = o2;
                    }
                    long idx = ((long)(bq * HH + h) * SS + sq) * DH + d;
                    bf16 h1 = __float2bfloat16(x1);
                    bf16 h2 = __float2bfloat16(x2);
                    __nv_bfloat162 hp = __halves2bfloat162(h1, h2);
                    *(uint32_t*)(Yh + idx) = *(uint32_t*)&hp;
                    bf16 l1 = __float2bfloat16(x1 - __bfloat162float(h1));
                    bf16 l2 = __float2bfloat16(x2 - __bfloat162float(h2));
                    __nv_bfloat162 lp = __halves2bfloat162(l1, l2);
                    *(uint32_t*)(Yl + idx) = *(uint32_t*)&lp;
                }
            }
        }
    }
}

// ---------------------------------------------------------------------------
// MMA flash attention (unchanged -- proven in rounds 10/11).
// ---------------------------------------------------------------------------
__global__ void __launch_bounds__(128) attn_mma(
    const bf16* __restrict__ Qh, const bf16* __restrict__ Ql,
    const bf16* __restrict__ Kh, const bf16* __restrict__ Kl,
    const bf16* __restrict__ Vh, const bf16* __restrict__ Vl,
    bf16* __restrict__ Ch, bf16* __restrict__ Cl)
{
    __shared__ __align__(16) bf16 sKh[2][32][72];
    __shared__ __align__(16) bf16 sKl[2][32][72];
    __shared__ __align__(16) bf16 sVh[2][64][40];   // transposed [d][key]
    __shared__ __align__(16) bf16 sVl[2][64][40];

    const int tid = threadIdx.x;
    const int w = tid >> 5, l = tid & 31;
    const int g = l >> 2, t = l & 3;
    const int bh = blockIdx.y, b = bh >> 4, h = bh & 15;
    const long hoff = (long)bh * SS * DH;

    const int krow = tid >> 2, kseg = tid & 3;
    const int vkp = tid & 15, vdc = tid >> 4;
    const float scale = 0.125f;

    for (int sel = 0; sel < 2; sel++) {
        const int qi = sel ? 31 - (int)blockIdx.x : (int)blockIdx.x;
        const int q0 = qi * 64;
        const int r0 = q0 + w * 16 + g;
        const int r1 = r0 + 8;

        uint32_t qfh[4][4], qfl[4][4];
        {
            const bf16* p0h = Qh + hoff + (long)r0 * DH;
            const bf16* p1h = Qh + hoff + (long)r1 * DH;
            const bf16* p0l = Ql + hoff + (long)r0 * DH;
            const bf16* p1l = Ql + hoff + (long)r1 * DH;
#pragma unroll
            for (int kc = 0; kc < 4; kc++) {
                int o0 = kc * 16 + 2 * t;
                qfh[kc][0] = *(const uint32_t*)(p0h + o0);
                qfh[kc][1] = *(const uint32_t*)(p1h + o0);
                qfh[kc][2] = *(const uint32_t*)(p0h + o0 + 8);
                qfh[kc][3] = *(const uint32_t*)(p1h + o0 + 8);
                qfl[kc][0] = *(const uint32_t*)(p0l + o0);
                qfl[kc][1] = *(const uint32_t*)(p1l + o0);
                qfl[kc][2] = *(const uint32_t*)(p0l + o0 + 8);
                qfl[kc][3] = *(const uint32_t*)(p1l + o0 + 8);
            }
        }

        float o[8][4];
#pragma unroll
        for (int nf = 0; nf < 8; nf++)
#pragma unroll
            for (int e = 0; e < 4; e++) o[nf][e] = 0.f;
        float mrun0 = -INFINITY, mrun1 = -INFINITY;
        float lrun0 = 0.f, lrun1 = 0.f;

        const int ktiles = 2 * qi + 2;
        for (int kt = 0; kt < ktiles; kt++) {
            const int k0 = kt * 32;
            const int buf = kt & 1;

            {
                const float4* sh = (const float4*)(Kh + hoff +
                                   (long)(k0 + krow) * DH + kseg * 16);
                const float4* sl = (const float4*)(Kl + hoff +
                                   (long)(k0 + krow) * DH + kseg * 16);
                *(float4*)&sKh[buf][krow][kseg * 16]     = sh[0];
                *(float4*)&sKh[buf][krow][kseg * 16 + 8] = sh[1];
                *(float4*)&sKl[buf][krow][kseg * 16]     = sl[0];
                *(float4*)&sKl[buf][krow][kseg * 16 + 8] = sl[1];
            }
            {
                const uint32_t* r0h = (const uint32_t*)(Vh + hoff +
                                      (long)(k0 + 2 * vkp) * DH + vdc * 8);
                const uint32_t* r1h = (const uint32_t*)(Vh + hoff +
                                      (long)(k0 + 2 * vkp + 1) * DH + vdc * 8);
                const uint32_t* r0l = (const uint32_t*)(Vl + hoff +
                                      (long)(k0 + 2 * vkp) * DH + vdc * 8);
                const uint32_t* r1l = (const uint32_t*)(Vl + hoff +
                                      (long)(k0 + 2 * vkp + 1) * DH + vdc * 8);
#pragma unroll
                for (int m = 0; m < 4; m++) {
                    uint32_t ah_ = r0h[m], bh_ = r1h[m];
                    uint32_t al_ = r0l[m], bl_ = r1l[m];
                    int d0 = vdc * 8 + 2 * m;
                    *(uint32_t*)&sVh[buf][d0][2 * vkp]     = __byte_perm(ah_, bh_, 0x5410);
                    *(uint32_t*)&sVh[buf][d0 + 1][2 * vkp] = __byte_perm(ah_, bh_, 0x7632);
                    *(uint32_t*)&sVl[buf][d0][2 * vkp]     = __byte_perm(al_, bl_, 0x5410);
                    *(uint32_t*)&sVl[buf][d0 + 1][2 * vkp] = __byte_perm(al_, bl_, 0x7632);
                }
            }
            __syncthreads();

            float sc[4][4];
#pragma unroll
            for (int nf = 0; nf < 4; nf++) {
#pragma unroll
                for (int e = 0; e < 4; e++) sc[nf][e] = 0.f;
#pragma unroll
                for (int kc = 0; kc < 4; kc++) {
                    const bf16* kh_ = &sKh[buf][nf * 8 + g][kc * 16 + 2 * t];
                    const bf16* kl_ = &sKl[buf][nf * 8 + g][kc * 16 + 2 * t];
                    uint32_t Bh2[2] = { *(const uint32_t*)kh_,
                                        *(const uint32_t*)(kh_ + 8) };
                    uint32_t Bl2[2] = { *(const uint32_t*)kl_,
                                        *(const uint32_t*)(kl_ + 8) };
                    mma16816(sc[nf], qfh[kc], Bh2);
                    mma16816(sc[nf], qfh[kc], Bl2);
                    mma16816(sc[nf], qfl[kc], Bh2);
                }
            }
            float rmax0 = -INFINITY, rmax1 = -INFINITY;
#pragma unroll
            for (int nf = 0; nf < 4; nf++) {
                int cb = k0 + nf * 8 + 2 * t;
                sc[nf][0] = (cb     <= r0) ? sc[nf][0] * scale : -INFINITY;
                sc[nf][1] = (cb + 1 <= r0) ? sc[nf][1] * scale : -INFINITY;
                sc[nf][2] = (cb     <= r1) ? sc[nf][2] * scale : -INFINITY;
                sc[nf][3] = (cb + 1 <= r1) ? sc[nf][3] * scale : -INFINITY;
                rmax0 = fmaxf(rmax0, fmaxf(sc[nf][0], sc[nf][1]));
                rmax1 = fmaxf(rmax1, fmaxf(sc[nf][2], sc[nf][3]));
            }
            rmax0 = fmaxf(rmax0, __shfl_xor_sync(0xffffffffu, rmax0, 1));
            rmax0 = fmaxf(rmax0, __shfl_xor_sync(0xffffffffu, rmax0, 2));
            rmax1 = fmaxf(rmax1, __shfl_xor_sync(0xffffffffu, rmax1, 1));
            rmax1 = fmaxf(rmax1, __shfl_xor_sync(0xffffffffu, rmax1, 2));

            float mnew0 = fmaxf(mrun0, rmax0);
            float mnew1 = fmaxf(mrun1, rmax1);
            float corr0 = __expf(mrun0 - mnew0);
            float corr1 = __expf(mrun1 - mnew1);

            float p[4][4];
            float ls0 = 0.f, ls1 = 0.f;
#pragma unroll
            for (int nf = 0; nf < 4; nf++) {
                p[nf][0] = __expf(sc[nf][0] - mnew0);
                p[nf][1] = __expf(sc[nf][1] - mnew0);
                p[nf][2] = __expf(sc[nf][2] - mnew1);
                p[nf][3] = __expf(sc[nf][3] - mnew1);
                ls0 += p[nf][0] + p[nf][1];
                ls1 += p[nf][2] + p[nf][3];
            }
            ls0 += __shfl_xor_sync(0xffffffffu, ls0, 1);
            ls0 += __shfl_xor_sync(0xffffffffu, ls0, 2);
            ls1 += __shfl_xor_sync(0xffffffffu, ls1, 1);
            ls1 += __shfl_xor_sync(0xffffffffu, ls1, 2);
            lrun0 = lrun0 * corr0 + ls0;
            lrun1 = lrun1 * corr1 + ls1;

#pragma unroll
            for (int nf = 0; nf < 8; nf++) {
                o[nf][0] *= corr0; o[nf][1] *= corr0;
                o[nf][2] *= corr1; o[nf][3] *= corr1;
            }

            uint32_t pfh[2][4], pfl[2][4];
#pragma unroll
            for (int kc2 = 0; kc2 < 2; kc2++) {
                const float* pa = p[2 * kc2];
                const float* pb = p[2 * kc2 + 1];
                float v0, v1, h0f, h1f;
#pragma unroll
                for (int e = 0; e < 4; e++) {
                    const float* src = (e & 2) ? pb : pa;
                    v0 = (e & 1) ? src[2] : src[0];
                    v1 = (e & 1) ? src[3] : src[1];
                    pfh[kc2][e] = pack_bf2(v0, v1);
                    __nv_bfloat162 hp = *(__nv_bfloat162*)&pfh[kc2][e];
                    h0f = __bfloat162float(hp.x);
                    h1f = __bfloat162float(hp.y);
                    pfl[kc2][e] = pack_bf2(v0 - h0f, v1 - h1f);
                }
            }

#pragma unroll
            for (int kc2 = 0; kc2 < 2; kc2++) {
#pragma unroll
                for (int nf = 0; nf < 8; nf++) {
                    const bf16* vh_ = &sVh[buf][nf * 8 + g][kc2 * 16 + 2 * t];
                    const bf16* vl_ = &sVl[buf][nf * 8 + g][kc2 * 16 + 2 * t];
                    uint32_t Bh2[2] = { *(const uint32_t*)vh_,
                                        *(const uint32_t*)(vh_ + 8) };
                    uint32_t Bl2[2] = { *(const uint32_t*)vl_,
                                        *(const uint32_t*)(vl_ + 8) };
                    mma16816(o[nf], pfh[kc2], Bh2);
                    mma16816(o[nf], pfh[kc2], Bl2);
                    mma16816(o[nf], pfl[kc2], Bh2);
                }
            }
            mrun0 = mnew0;
            mrun1 = mnew1;
        }

        float inv0 = 1.f / lrun0, inv1 = 1.f / lrun1;
        long base0 = ((long)(b * SS + r0) * HH + h) * DH;
        long base1 = ((long)(b * SS + r1) * HH + h) * DH;
#pragma unroll
        for (int nf = 0; nf < 8; nf++) {
            int d = nf * 8 + 2 * t;
            float x0 = o[nf][0] * inv0, x1 = o[nf][1] * inv0;
            float x2 = o[nf][2] * inv1, x3 = o[nf][3] * inv1;
            uint32_t h01 = pack_bf2(x0, x1);
            uint32_t h23 = pack_bf2(x2, x3);
            __nv_bfloat162 hp0 = *(__nv_bfloat162*)&h01;
            __nv_bfloat162 hp1 = *(__nv_bfloat162*)&h23;
            uint32_t l01 = pack_bf2(x0 - __bfloat162float(hp0.x),
                                    x1 - __bfloat162float(hp0.y));
            uint32_t l23 = pack_bf2(x2 - __bfloat162float(hp1.x),
                                    x3 - __bfloat162float(hp1.y));
            *(uint32_t*)(Ch + base0 + d) = h01;
            *(uint32_t*)(Cl + base0 + d) = l01;
            *(uint32_t*)(Ch + base1 + d) = h23;
            *(uint32_t*)(Cl + base1 + d) = l23;
        }
    }
}

// ---------------------------------------------------------------------------
extern "C" void kernel_launch(void* const* d_in, const int* in_sizes, int n_in,
                              void* d_out, int out_size)
{
    (void)in_sizes; (void)n_in; (void)out_size;
    const float* x   = (const float*)d_in[0];
    const int*   pos = (const int*)  d_in[1];
    const float* w[4] = { (const float*)d_in[2], (const float*)d_in[3],
                          (const float*)d_in[4], (const float*)d_in[5] };
    float* out = (float*)d_out;

    bf16 *qh, *ql, *kh, *kl, *vh, *vl, *xh, *xl, *ch, *cl, *wh, *wl;
    cudaGetSymbolAddress((void**)&qh, g_qh);
    cudaGetSymbolAddress((void**)&ql, g_ql);
    cudaGetSymbolAddress((void**)&kh, g_kh);
    cudaGetSymbolAddress((void**)&kl, g_kl);
    cudaGetSymbolAddress((void**)&vh, g_vh);
    cudaGetSymbolAddress((void**)&vl, g_vl);
    cudaGetSymbolAddress((void**)&xh, g_xh);
    cudaGetSymbolAddress((void**)&xl, g_xl);
    cudaGetSymbolAddress((void**)&ch, g_ch);
    cudaGetSymbolAddress((void**)&cl, g_cl);
    cudaGetSymbolAddress((void**)&wh, g_wh);
    cudaGetSymbolAddress((void**)&wl, g_wl);

    cudaFuncSetAttribute(gemm_mma, cudaFuncAttributeMaxDynamicSharedMemorySize,
                         GSMEM);

    const int nX4 = BB * SS * DD / 4;
    split_kernel<<<(nX4 + 255) / 256, 256>>>(x, xh, xl, nX4);
    const int nW4 = DD * DD / 4;
    for (int i = 0; i < 4; i++)
        split_kernel<<<(nW4 + 255) / 256, 256>>>(w[i], wh + (size_t)i * DD * DD,
                                                 wl + (size_t)i * DD * DD, nW4);

    dim3 gg(DD / 128, (BB * SS) / 128);   // 8 x 64
    gemm_mma<<<gg, 512, GSMEM>>>(xh, xl, wh + 0 * (size_t)DD * DD,
                                 wl + 0 * (size_t)DD * DD,
                                 nullptr, qh, ql, pos, 2);   // Q + RoPE
    gemm_mma<<<gg, 512, GSMEM>>>(xh, xl, wh + 1 * (size_t)DD * DD,
                                 wl + 1 * (size_t)DD * DD,
                                 nullptr, kh, kl, pos, 2);   // K + RoPE
    gemm_mma<<<gg, 512, GSMEM>>>(xh, xl, wh + 2 * (size_t)DD * DD,
                                 wl + 2 * (size_t)DD * DD,
                                 nullptr, vh, vl, pos, 1);   // V

    dim3 ga(16, BB * HH);                 // paired causal q-tiles (qi, 31-qi)
    attn_mma<<<ga, 128>>>(qh, ql, kh, kl, vh, vl, ch, cl);

    gemm_mma<<<gg, 512, GSMEM>>>(ch, cl, wh + 3 * (size_t)DD * DD,
                                 wl + 3 * (size_t)DD * DD,
                                 out, nullptr, nullptr, pos, 0);  // Wo
}